// round 9
// baseline (speedup 1.0000x reference)
#include <cuda_runtime.h>
#include <cuda_bf16.h>
#include <cstdint>

// Problem constants: B=1, CIN=COUT=64, H=W=256, K=3, stride=1, pad=1.
#define IMG_H 256
#define IMG_W 256

// ---- device scratch (no allocation allowed) ----
__device__ float g_xT[IMG_H * IMG_W * 64];   // x as (y, x, c) fp32
__device__ uint4 g_wh[9 * 512];              // per-tap W tile [cout=64][cin=64] bf16, SW128-preswizzled, hi
__device__ uint4 g_wl[9 * 512];              // ... lo

typedef unsigned long long u64;

// ---- packed fp32x2 helpers ----
__device__ __forceinline__ u64 fma2(u64 a, u64 b, u64 c) {
    u64 d; asm("fma.rn.f32x2 %0, %1, %2, %3;" : "=l"(d) : "l"(a), "l"(b), "l"(c));
    return d;
}
__device__ __forceinline__ u64 mul2(u64 a, u64 b) {
    u64 d; asm("mul.rn.f32x2 %0, %1, %2;" : "=l"(d) : "l"(a), "l"(b));
    return d;
}
__device__ __forceinline__ u64 splat2(float x) {
    unsigned r = __float_as_uint(x);
    u64 d; asm("mov.b64 %0, {%1, %2};" : "=l"(d) : "r"(r), "r"(r));
    return d;
}
__device__ __forceinline__ float2 unpack2(u64 v) {
    unsigned lo, hi;
    asm("mov.b64 {%0, %1}, %2;" : "=r"(lo), "=r"(hi) : "l"(v));
    return make_float2(__uint_as_float(lo), __uint_as_float(hi));
}

// ---- tensor-core + async-copy helpers (sm_80 path; compiles for compute_100) ----
__device__ __forceinline__ uint32_t smem_u32_of(const void* p) {
    uint32_t a;
    asm("{ .reg .u64 t; cvta.to.shared.u64 t, %1; cvt.u32.u64 %0, t; }"
        : "=r"(a) : "l"(p));
    return a;
}
__device__ __forceinline__ void ldsm4(uint32_t* r, uint32_t addr) {
    asm volatile("ldmatrix.sync.aligned.m8n8.x4.shared.b16 {%0,%1,%2,%3}, [%4];"
        : "=r"(r[0]), "=r"(r[1]), "=r"(r[2]), "=r"(r[3]) : "r"(addr));
}
__device__ __forceinline__ void ldsm2(uint32_t* r, uint32_t addr) {
    asm volatile("ldmatrix.sync.aligned.m8n8.x2.shared.b16 {%0,%1}, [%2];"
        : "=r"(r[0]), "=r"(r[1]) : "r"(addr));
}
__device__ __forceinline__ void mma_bf16(float* c, const uint32_t* a, const uint32_t* b) {
    asm volatile(
        "mma.sync.aligned.m16n8k16.row.col.f32.bf16.bf16.f32 "
        "{%0,%1,%2,%3}, {%4,%5,%6,%7}, {%8,%9}, {%0,%1,%2,%3};"
        : "+f"(c[0]), "+f"(c[1]), "+f"(c[2]), "+f"(c[3])
        : "r"(a[0]), "r"(a[1]), "r"(a[2]), "r"(a[3]), "r"(b[0]), "r"(b[1]));
}
__device__ __forceinline__ void cpasync16(uint32_t dst, const void* src) {
    asm volatile("cp.async.cg.shared.global [%0], [%1], 16;" :: "r"(dst), "l"(src));
}
#define CP_COMMIT() asm volatile("cp.async.commit_group;" ::: "memory")
#define CP_WAIT0()  asm volatile("cp.async.wait_group 0;" ::: "memory")

// ---- smem layout (bytes from dynamic base) ----
#define OFF_BIAS   0         // 64 floats
#define OFF_TILE   1024      // halo fp32: 11*11*64*4 = 30976
#define OFF_A      32768     // A bufs: 2 x (hi 8192 + lo 8192) = 32768
#define OFF_W      65536     // W bufs: 2 x (hi 8192 + lo 8192) = 32768
#define SMEM_TOTAL 98304

// ============================================================
// Kernel 1: transpose x (C,H,W)->(H,W,C)  +  weight split/relayout (merged)
// ============================================================
__global__ void prep_kernel(const float* __restrict__ x,
                            const float* __restrict__ wsrc) {
    __shared__ float ts[64][65];
    const int t  = threadIdx.x;

    // weight prep: first 144 blocks handle 256 weights each (64*64*9 = 36864)
    if (blockIdx.x < 144) {
        int idx  = blockIdx.x * 256 + t;
        int cout = idx / 576;
        int r    = idx - cout * 576;
        int cin  = r / 9;
        int k    = r - cin * 9;
        float v  = wsrc[idx];
        __nv_bfloat16 hb = __float2bfloat16(v);
        float hv = __bfloat162float(hb);
        __nv_bfloat16 lb = __float2bfloat16(v - hv);
        uint32_t off = (cout << 7) + (cin << 1);
        uint32_t sw  = off ^ ((off >> 3) & 0x70);
        ((__nv_bfloat16*)g_wh)[k * 4096 + (sw >> 1)] = hb;
        ((__nv_bfloat16*)g_wl)[k * 4096 + (sw >> 1)] = lb;
    }

    // transpose
    const int tx = t & 63;
    const int ty = t >> 6;
    const int P0 = blockIdx.x * 64;
#pragma unroll
    for (int i = 0; i < 16; ++i) {
        int c = (i << 2) + ty;
        ts[c][tx] = x[c * (IMG_H * IMG_W) + P0 + tx];
    }
    __syncthreads();
#pragma unroll
    for (int i = 0; i < 16; ++i) {
        int p = (i << 2) + ty;
        g_xT[(P0 + p) * 64 + tx] = ts[tx][p];
    }
}

// ============================================================
// Bilinear sample of one tap into a bf16 hi/lo A tile (SW128 swizzled).
// 4 threads per pixel, 4 channel-quads each.
// ============================================================
__device__ __forceinline__ void sample_tap(
    char* smc_, const float* __restrict__ tile, uint32_t abuf_off,
    int ky, int kx, float offy, float offx,
    int gy, int gx, int Y0, int X0, int px, int qbase)
{
    float pyf = (float)(gy - 1 + ky) + offy;
    float pxf = (float)(gx - 1 + kx) + offx;
    float y0f = floorf(pyf), x0f = floorf(pxf);
    int   y0  = (int)y0f,   x0  = (int)x0f;
    float wy1 = pyf - y0f,  wx1 = pxf - x0f;
    float wy0 = 1.f - wy1,  wx0 = 1.f - wx1;
    int iy = y0 - (Y0 - 1);
    int ix = x0 - (X0 - 1);
    float fy0 = ((unsigned)y0       < (unsigned)IMG_H && (unsigned)iy       <=  9u) ? 1.f : 0.f;
    float fy1 = ((unsigned)(y0 + 1) < (unsigned)IMG_H && (unsigned)(iy + 1) <= 10u) ? 1.f : 0.f;
    float fx0 = ((unsigned)x0       < (unsigned)IMG_W && (unsigned)ix       <=  9u) ? 1.f : 0.f;
    float fx1 = ((unsigned)(x0 + 1) < (unsigned)IMG_W && (unsigned)(ix + 1) <= 10u) ? 1.f : 0.f;
    u64 W00 = splat2(wy0 * wx0 * fy0 * fx0);
    u64 W01 = splat2(wy0 * wx1 * fy0 * fx1);
    u64 W10 = splat2(wy1 * wx0 * fy1 * fx0);
    u64 W11 = splat2(wy1 * wx1 * fy1 * fx1);
    int iyc = min(max(iy, 0), 9);
    int ixc = min(max(ix, 0), 9);
    int c00 = iyc * 11 + ixc;
    int c01 = c00 + 1;
    int c10 = c00 + 11;
    int c11 = c00 + 12;
    char* abase = smc_ + abuf_off;
#pragma unroll
    for (int qq = 0; qq < 4; ++qq) {
        int q = qbase + qq;
        ulonglong2 v00 = *reinterpret_cast<const ulonglong2*>(
            &tile[(c00 << 6) + ((q ^ (c00 & 7)) << 2)]);
        ulonglong2 v01 = *reinterpret_cast<const ulonglong2*>(
            &tile[(c01 << 6) + ((q ^ (c01 & 7)) << 2)]);
        ulonglong2 v10 = *reinterpret_cast<const ulonglong2*>(
            &tile[(c10 << 6) + ((q ^ (c10 & 7)) << 2)]);
        ulonglong2 v11 = *reinterpret_cast<const ulonglong2*>(
            &tile[(c11 << 6) + ((q ^ (c11 & 7)) << 2)]);
        u64 lo2 = fma2(v00.x, W00, fma2(v01.x, W01, fma2(v10.x, W10, mul2(v11.x, W11))));
        u64 hi2 = fma2(v00.y, W00, fma2(v01.y, W01, fma2(v10.y, W10, mul2(v11.y, W11))));
        float2 fa = unpack2(lo2);   // ch q*4+0, +1
        float2 fb = unpack2(hi2);   // ch q*4+2, +3
        uint32_t h01, h23;
        asm("cvt.rn.satfinite.bf16x2.f32 %0, %1, %2;" : "=r"(h01) : "f"(fa.y), "f"(fa.x));
        asm("cvt.rn.satfinite.bf16x2.f32 %0, %1, %2;" : "=r"(h23) : "f"(fb.y), "f"(fb.x));
        float r0 = fa.x - __uint_as_float(h01 << 16);
        float r1 = fa.y - __uint_as_float(h01 & 0xffff0000u);
        float r2 = fb.x - __uint_as_float(h23 << 16);
        float r3 = fb.y - __uint_as_float(h23 & 0xffff0000u);
        uint32_t l01, l23;
        asm("cvt.rn.satfinite.bf16x2.f32 %0, %1, %2;" : "=r"(l01) : "f"(r1), "f"(r0));
        asm("cvt.rn.satfinite.bf16x2.f32 %0, %1, %2;" : "=r"(l23) : "f"(r3), "f"(r2));
        uint32_t aoff = (px << 7) + (q << 3);
        uint32_t sw   = aoff ^ ((aoff >> 3) & 0x70);
        *reinterpret_cast<uint2*>(abase + sw)        = make_uint2(h01, h23);
        *reinterpret_cast<uint2*>(abase + 8192 + sw) = make_uint2(l01, l23);
    }
}

// ============================================================
// Kernel 2: main — 8x8 px tile, 256 threads, 2 blocks/SM.
//   Single sync per tap; double-buffered A (samples) + W (weights, cp.async).
//   Per tap: sync -> MMA(k) [bufs k&1] -> sample(k+1) [bufs (k+1)&1].
// ============================================================
extern __shared__ char smc[];

__global__ __launch_bounds__(256, 2)
void deform_main_kernel(const float* __restrict__ offs,
                        const float* __restrict__ bias,
                        float* __restrict__ out) {
    float* tile = (float*)(smc + OFF_TILE);
    const uint32_t smb = smem_u32_of(smc);

    const int t    = threadIdx.x;
    const int lane = t & 31;
    const int wid  = t >> 5;
    const int X0   = blockIdx.x << 3;
    const int Y0   = blockIdx.y << 3;

    if (t < 64) ((float*)(smc + OFF_BIAS))[t] = bias[t];

    // sampling identity: 4 threads per pixel (16 channels = 4 quads each)
    const int px    = t & 63;
    const int qbase = (t >> 6) << 2;
    const int gy    = Y0 + (px >> 3);
    const int gx    = X0 + (px & 7);
    const int pixidx = (gy << 8) + gx;

    // tap-0 offsets (issued early, consumed after halo sync)
    float oy0 = offs[pixidx];
    float ox0 = offs[(1 << 16) + pixidx];

    // ---- halo tile: 11x11 cells x 64 ch fp32 (zero outside image) ----
    for (int f = t; f < 121 * 16; f += 256) {
        int cell = f >> 4;
        int q    = f & 15;
        int rr   = cell / 11;
        int cc   = cell - rr * 11;
        int hy   = Y0 - 1 + rr;
        int hx   = X0 - 1 + cc;
        float4 v = make_float4(0.f, 0.f, 0.f, 0.f);
        if ((unsigned)hy < (unsigned)IMG_H && (unsigned)hx < (unsigned)IMG_W)
            v = *reinterpret_cast<const float4*>(
                    &g_xT[(((hy << 8) + hx) << 6) + (q << 2)]);
        *reinterpret_cast<float4*>(
            &tile[(cell << 6) + ((q ^ (cell & 7)) << 2)]) = v;
    }

    // ---- W0 async copy ----
    {
        uint32_t wdst = smb + OFF_W;
        cpasync16(wdst +         (t << 4), g_wh + t);
        cpasync16(wdst + 4096  + (t << 4), g_wh + 256 + t);
        cpasync16(wdst + 8192  + (t << 4), g_wl + t);
        cpasync16(wdst + 12288 + (t << 4), g_wl + 256 + t);
        CP_COMMIT();
    }
    CP_WAIT0();
    __syncthreads();     // halo + W0 visible

    // ---- sample tap 0 into A buf 0 ----
    sample_tap(smc, tile, OFF_A, 0, 0, oy0, ox0, gy, gx, Y0, X0, px, qbase);

    // mma identity
    const int lane7  = lane & 7;
    const int a_row0 = (lane & 7) + (lane & 8);
    const int a_kbit = lane >> 4;
    const int b_rowl = (wid << 3) + (lane & 7);
    const int b_kbit = (lane >> 3) & 1;

    float acc[4][4];
#pragma unroll
    for (int m = 0; m < 4; ++m)
#pragma unroll
        for (int j = 0; j < 4; ++j) acc[m][j] = 0.f;

#pragma unroll 1
    for (int k = 0; k < 9; ++k) {
        const int s  = k & 1;
        const int s1 = s ^ 1;

        // prefetch offsets for tap k+1 (consumed at end of this iteration)
        float nx_oy = 0.f, nx_ox = 0.f;
        if (k < 8) {
            nx_oy = offs[(((k + 1) * 2    ) << 16) + pixidx];
            nx_ox = offs[(((k + 1) * 2 + 1) << 16) + pixidx];
        }

        CP_WAIT0();          // W(k) copies landed (this thread's)
        __syncthreads();     // A(k) + W(k) visible; bufs s1 free (MMA(k-1) done)

        // launch W(k+1) into the now-free W buffer (hidden behind MMA+sampling)
        if (k < 8) {
            uint32_t wdst = smb + OFF_W + s1 * 16384;
            const uint4* wh = g_wh + (k + 1) * 512;
            const uint4* wl = g_wl + (k + 1) * 512;
            cpasync16(wdst +         (t << 4), wh + t);
            cpasync16(wdst + 4096  + (t << 4), wh + 256 + t);
            cpasync16(wdst + 8192  + (t << 4), wl + t);
            cpasync16(wdst + 12288 + (t << 4), wl + 256 + t);
            CP_COMMIT();
        }

        // ---- MMA(k): 48 HMMA per warp (hh + hl + lh) ----
        {
            uint32_t Ab = smb + OFF_A + s * 16384;
            uint32_t Wb = smb + OFF_W + s * 16384;
#pragma unroll
            for (int kt = 0; kt < 4; ++kt) {
                uint32_t bh[2], bl[2];
                uint32_t ba = Ab + ((uint32_t)b_rowl << 7)
                            + (uint32_t)(((kt * 2 + b_kbit) ^ lane7) << 4);
                ldsm2(bh, ba);
                ldsm2(bl, ba + 8192);
#pragma unroll
                for (int mt = 0; mt < 4; ++mt) {
                    uint32_t ah[4], al[4];
                    uint32_t aa = Wb + (((uint32_t)(mt * 16 + a_row0)) << 7)
                                + (uint32_t)(((kt * 2 + a_kbit) ^ lane7) << 4);
                    ldsm4(ah, aa);
                    ldsm4(al, aa + 8192);
                    mma_bf16(acc[mt], ah, bh);
                    mma_bf16(acc[mt], ah, bl);
                    mma_bf16(acc[mt], al, bh);
                }
            }
        }

        // ---- sample tap k+1 into A buf s1 (overlaps other warps' MMA) ----
        if (k < 8) {
            int kn = k + 1;
            int ky = kn / 3;
            int kx = kn - ky * 3;
            sample_tap(smc, tile, OFF_A + s1 * 16384, ky, kx, nx_oy, nx_ox,
                       gy, gx, Y0, X0, px, qbase);
        }
    }

    // ---- epilogue: bias + float2 stores (no sync needed; acc is warp-local) ----
    {
        const float* sbias = (const float*)(smc + OFF_BIAS);
        int tg  = lane >> 2;
        int tc2 = (lane & 3) << 1;
        int pix = ((Y0 + wid) << 8) + X0 + tc2;
#pragma unroll
        for (int mt = 0; mt < 4; ++mt) {
            int c0 = mt * 16 + tg;
            int c1 = c0 + 8;
            float b0 = sbias[c0], b1 = sbias[c1];
            *reinterpret_cast<float2*>(&out[(c0 << 16) + pix]) =
                make_float2(acc[mt][0] + b0, acc[mt][1] + b0);
            *reinterpret_cast<float2*>(&out[(c1 << 16) + pix]) =
                make_float2(acc[mt][2] + b1, acc[mt][3] + b1);
        }
    }
}

// ============================================================
// Launch
// ============================================================
extern "C" void kernel_launch(void* const* d_in, const int* in_sizes, int n_in,
                              void* d_out, int out_size) {
    const float* x      = nullptr;
    const float* offset = nullptr;
    const float* weight = nullptr;
    const float* bias   = nullptr;

    for (int i = 0; i < n_in; ++i) {
        switch (in_sizes[i]) {
            case 64 * 256 * 256: x      = (const float*)d_in[i]; break;
            case 18 * 256 * 256: offset = (const float*)d_in[i]; break;
            case 64 * 64 * 9:    weight = (const float*)d_in[i]; break;
            case 64:             bias   = (const float*)d_in[i]; break;
            default: break;
        }
    }
    if (!x || !offset || !weight || !bias) {
        x      = (const float*)d_in[0];
        offset = (const float*)d_in[1];
        weight = (const float*)d_in[2];
        bias   = (const float*)d_in[3];
    }

    cudaFuncSetAttribute(deform_main_kernel,
                         cudaFuncAttributeMaxDynamicSharedMemorySize, SMEM_TOTAL);

    prep_kernel<<<(IMG_H * IMG_W) / 64, 256>>>(x, weight);
    deform_main_kernel<<<dim3(IMG_W / 8, IMG_H / 8), 256, SMEM_TOTAL>>>(
        offset, bias, (float*)d_out);
}

// round 10
// speedup vs baseline: 1.0234x; 1.0234x over previous
#include <cuda_runtime.h>
#include <cuda_bf16.h>
#include <cstdint>

// Problem constants: B=1, CIN=COUT=64, H=W=256, K=3, stride=1, pad=1.
#define IMG_H 256
#define IMG_W 256

// ---- device scratch (no allocation allowed) ----
__device__ float g_xT[IMG_H * IMG_W * 64];   // x as (y, x, c) fp32
__device__ uint4 g_wh[9 * 512];              // per-tap W tile [cout=64][cin=64] bf16, SW128-preswizzled, hi
__device__ uint4 g_wl[9 * 512];              // ... lo

typedef unsigned long long u64;

// ---- packed fp32x2 helpers ----
__device__ __forceinline__ u64 fma2(u64 a, u64 b, u64 c) {
    u64 d; asm("fma.rn.f32x2 %0, %1, %2, %3;" : "=l"(d) : "l"(a), "l"(b), "l"(c));
    return d;
}
__device__ __forceinline__ u64 mul2(u64 a, u64 b) {
    u64 d; asm("mul.rn.f32x2 %0, %1, %2;" : "=l"(d) : "l"(a), "l"(b));
    return d;
}
__device__ __forceinline__ u64 splat2(float x) {
    unsigned r = __float_as_uint(x);
    u64 d; asm("mov.b64 %0, {%1, %2};" : "=l"(d) : "r"(r), "r"(r));
    return d;
}
__device__ __forceinline__ float2 unpack2(u64 v) {
    unsigned lo, hi;
    asm("mov.b64 {%0, %1}, %2;" : "=r"(lo), "=r"(hi) : "l"(v));
    return make_float2(__uint_as_float(lo), __uint_as_float(hi));
}

// ---- tensor-core + async-copy helpers (sm_80 path; compiles for compute_100) ----
__device__ __forceinline__ uint32_t smem_u32_of(const void* p) {
    uint32_t a;
    asm("{ .reg .u64 t; cvta.to.shared.u64 t, %1; cvt.u32.u64 %0, t; }"
        : "=r"(a) : "l"(p));
    return a;
}
__device__ __forceinline__ void ldsm4(uint32_t* r, uint32_t addr) {
    asm volatile("ldmatrix.sync.aligned.m8n8.x4.shared.b16 {%0,%1,%2,%3}, [%4];"
        : "=r"(r[0]), "=r"(r[1]), "=r"(r[2]), "=r"(r[3]) : "r"(addr));
}
__device__ __forceinline__ void mma2(float* c, const uint32_t* a,
                                     uint32_t b0, uint32_t b1) {
    asm volatile(
        "mma.sync.aligned.m16n8k16.row.col.f32.bf16.bf16.f32 "
        "{%0,%1,%2,%3}, {%4,%5,%6,%7}, {%8,%9}, {%0,%1,%2,%3};"
        : "+f"(c[0]), "+f"(c[1]), "+f"(c[2]), "+f"(c[3])
        : "r"(a[0]), "r"(a[1]), "r"(a[2]), "r"(a[3]), "r"(b0), "r"(b1));
}
__device__ __forceinline__ void cpasync16(uint32_t dst, const void* src) {
    asm volatile("cp.async.cg.shared.global [%0], [%1], 16;" :: "r"(dst), "l"(src));
}
#define CP_COMMIT() asm volatile("cp.async.commit_group;" ::: "memory")
#define CP_WAIT0()  asm volatile("cp.async.wait_group 0;" ::: "memory")

// ---- smem layout (bytes from dynamic base) ----
#define OFF_BIAS   0          // 64 floats
#define OFF_TILE   1024       // halo fp32: 19*11*64*4 = 53504
#define OFF_W      54528      // W bufs: 2 x (hi 8192 + lo 8192) = 32768
#define SMEM_TOTAL 87296

// ============================================================
// Kernel 1: transpose x (C,H,W)->(H,W,C)  +  weight split/relayout (merged)
// ============================================================
__global__ void prep_kernel(const float* __restrict__ x,
                            const float* __restrict__ wsrc) {
    __shared__ float ts[64][65];
    const int t = threadIdx.x;

    // weight prep: first 144 blocks handle 256 weights each (64*64*9 = 36864)
    if (blockIdx.x < 144) {
        int idx  = blockIdx.x * 256 + t;
        int cout = idx / 576;
        int r    = idx - cout * 576;
        int cin  = r / 9;
        int k    = r - cin * 9;
        float v  = wsrc[idx];
        __nv_bfloat16 hb = __float2bfloat16(v);
        float hv = __bfloat162float(hb);
        __nv_bfloat16 lb = __float2bfloat16(v - hv);
        uint32_t off = (cout << 7) + (cin << 1);
        uint32_t sw  = off ^ ((off >> 3) & 0x70);
        ((__nv_bfloat16*)g_wh)[k * 4096 + (sw >> 1)] = hb;
        ((__nv_bfloat16*)g_wl)[k * 4096 + (sw >> 1)] = lb;
    }

    // transpose
    const int tx = t & 63;
    const int ty = t >> 6;
    const int P0 = blockIdx.x * 64;
#pragma unroll
    for (int i = 0; i < 16; ++i) {
        int c = (i << 2) + ty;
        ts[c][tx] = x[c * (IMG_H * IMG_W) + P0 + tx];
    }
    __syncthreads();
#pragma unroll
    for (int i = 0; i < 16; ++i) {
        int p = (i << 2) + ty;
        g_xT[(P0 + p) * 64 + tx] = ts[tx][p];
    }
}

// ============================================================
// Sample one pixel's 16 fragment channels (c = lane&3 selects
// {2c,2c+1,2c+8,2c+9}+16kt) directly into B-fragment registers.
// BH/BL layout: [kt*2 + h] where h=0 -> b0 (k%16<8), h=1 -> b1.
// ============================================================
__device__ __forceinline__ void sample_px(
    const char* __restrict__ tileb, int c, int ky, int kx,
    float offy, float offx, int gy, int gx, int Y0, int X0,
    uint32_t* BH, uint32_t* BL)
{
    float pyf = (float)(gy - 1 + ky) + offy;
    float pxf = (float)(gx - 1 + kx) + offx;
    float y0f = floorf(pyf), x0f = floorf(pxf);
    int   y0  = (int)y0f,   x0  = (int)x0f;
    float wy1 = pyf - y0f,  wx1 = pxf - x0f;
    float wy0 = 1.f - wy1,  wx0 = 1.f - wx1;
    int iy = y0 - (Y0 - 1);
    int ix = x0 - (X0 - 1);
    float fy0 = ((unsigned)y0       < 256u && (unsigned)iy       <= 17u) ? 1.f : 0.f;
    float fy1 = ((unsigned)(y0 + 1) < 256u && (unsigned)(iy + 1) <= 18u) ? 1.f : 0.f;
    float fx0 = ((unsigned)x0       < 256u && (unsigned)ix       <=  9u) ? 1.f : 0.f;
    float fx1 = ((unsigned)(x0 + 1) < 256u && (unsigned)(ix + 1) <= 10u) ? 1.f : 0.f;
    u64 W00 = splat2(wy0 * wx0 * fy0 * fx0);
    u64 W01 = splat2(wy0 * wx1 * fy0 * fx1);
    u64 W10 = splat2(wy1 * wx0 * fy1 * fx0);
    u64 W11 = splat2(wy1 * wx1 * fy1 * fx1);
    int iyc = min(max(iy, 0), 17);
    int ixc = min(max(ix, 0), 9);
    int c00 = iyc * 11 + ixc;
    int c01 = c00 + 1;
    int c10 = c00 + 11;
    int c11 = c00 + 12;
    const char* p00 = tileb + (c00 << 8);
    const char* p01 = tileb + (c01 << 8);
    const char* p10 = tileb + (c10 << 8);
    const char* p11 = tileb + (c11 << 8);
    const int s00 = c00 & 7, s01 = c01 & 7, s10 = c10 & 7, s11 = c11 & 7;
    const uint32_t sub = (uint32_t)((c & 1) << 3);
    const int qb = c >> 1;
#pragma unroll
    for (int kt = 0; kt < 4; ++kt) {
#pragma unroll
        for (int h = 0; h < 2; ++h) {
            int q = 4 * kt + 2 * h + qb;
            u64 v00 = *(const u64*)(p00 + ((uint32_t)((q ^ s00) << 4) | sub));
            u64 v01 = *(const u64*)(p01 + ((uint32_t)((q ^ s01) << 4) | sub));
            u64 v10 = *(const u64*)(p10 + ((uint32_t)((q ^ s10) << 4) | sub));
            u64 v11 = *(const u64*)(p11 + ((uint32_t)((q ^ s11) << 4) | sub));
            u64 v = fma2(v00, W00, fma2(v01, W01, fma2(v10, W10, mul2(v11, W11))));
            float2 f = unpack2(v);
            uint32_t hreg, lreg;
            asm("cvt.rn.satfinite.bf16x2.f32 %0, %1, %2;" : "=r"(hreg) : "f"(f.y), "f"(f.x));
            float r0 = f.x - __uint_as_float(hreg << 16);
            float r1 = f.y - __uint_as_float(hreg & 0xffff0000u);
            asm("cvt.rn.satfinite.bf16x2.f32 %0, %1, %2;" : "=r"(lreg) : "f"(r1), "f"(r0));
            BH[kt * 2 + h] = hreg;
            BL[kt * 2 + h] = lreg;
        }
    }
}

// ============================================================
// Kernel 2: main — 16x8 px tile, 256 threads (8 warps), 2 blocks/SM.
//   Warp = 64 cout x 16 px (2 n-tiles). Samples go straight into
//   B-fragment registers (no A smem tile). W double-buffered (cp.async).
//   One __syncthreads per tap (W buffer handoff only).
// ============================================================
extern __shared__ char smc[];

__global__ __launch_bounds__(256, 2)
void deform_main_kernel(const float* __restrict__ offs,
                        const float* __restrict__ bias,
                        float* __restrict__ out) {
    const char* tileb = smc + OFF_TILE;
    float* tilef = (float*)(smc + OFF_TILE);
    const uint32_t smb = smem_u32_of(smc);

    const int t    = threadIdx.x;
    const int lane = t & 31;
    const int wid  = t >> 5;
    const int X0   = blockIdx.x << 3;      // 8 wide
    const int Y0   = blockIdx.y << 4;      // 16 tall

    if (t < 64) ((float*)(smc + OFF_BIAS))[t] = bias[t];

    // fragment/sampling identity: quad of lanes per pixel
    const int c    = lane & 3;             // channel group
    const int gx   = X0 + (lane >> 2);     // 0..7
    const int gy0  = Y0 + (wid << 1);      // rows wid*2 (nt=0), +1 (nt=1)
    const int pix0 = (gy0 << 8) + gx;
    const int pix1 = pix0 + 256;

    // tap-0 offsets
    float oy[2], ox[2];
    oy[0] = offs[pix0];  ox[0] = offs[(1 << 16) + pix0];
    oy[1] = offs[pix1];  ox[1] = offs[(1 << 16) + pix1];

    // ---- halo tile: 19x11 cells x 64 ch fp32 (zero outside image) ----
    for (int f = t; f < 209 * 16; f += 256) {
        int cell = f >> 4;
        int q    = f & 15;
        int rr   = cell / 11;
        int cc   = cell - rr * 11;
        int hy   = Y0 - 1 + rr;
        int hx   = X0 - 1 + cc;
        float4 v = make_float4(0.f, 0.f, 0.f, 0.f);
        if ((unsigned)hy < (unsigned)IMG_H && (unsigned)hx < (unsigned)IMG_W)
            v = *reinterpret_cast<const float4*>(
                    &g_xT[(((hy << 8) + hx) << 6) + (q << 2)]);
        *reinterpret_cast<float4*>(
            &tilef[(cell << 6) + ((q ^ (cell & 7)) << 2)]) = v;
    }

    // ---- W0 async copy ----
    {
        uint32_t wdst = smb + OFF_W;
        cpasync16(wdst +         (t << 4), g_wh + t);
        cpasync16(wdst + 4096  + (t << 4), g_wh + 256 + t);
        cpasync16(wdst + 8192  + (t << 4), g_wl + t);
        cpasync16(wdst + 12288 + (t << 4), g_wl + 256 + t);
        CP_COMMIT();
    }
    __syncthreads();     // halo visible (W0 waited inside loop)

    // mma W-operand identity (A operand = weights, m = cout)
    const int lane7  = lane & 7;
    const int a_row0 = (lane & 7) + (lane & 8);
    const int a_kbit = lane >> 4;

    float acc[4][2][4];
#pragma unroll
    for (int m = 0; m < 4; ++m)
#pragma unroll
        for (int n = 0; n < 2; ++n)
#pragma unroll
            for (int j = 0; j < 4; ++j) acc[m][n][j] = 0.f;

    uint32_t BH[2][8], BL[2][8];

#pragma unroll 1
    for (int k = 0; k < 9; ++k) {
        const int s  = k & 1;
        const int ky = k / 3;
        const int kx = k - ky * 3;

        // prefetch offsets for tap k+1
        float noy[2], nox[2];
        if (k < 8) {
            noy[0] = offs[(((k + 1) * 2    ) << 16) + pix0];
            nox[0] = offs[(((k + 1) * 2 + 1) << 16) + pix0];
            noy[1] = offs[(((k + 1) * 2    ) << 16) + pix1];
            nox[1] = offs[(((k + 1) * 2 + 1) << 16) + pix1];
        }

        // ---- sample tap k into B-fragment registers (halo only; no sync) ----
        sample_px(tileb, c, ky, kx, oy[0], ox[0], gy0,     gx, Y0, X0, BH[0], BL[0]);
        sample_px(tileb, c, ky, kx, oy[1], ox[1], gy0 + 1, gx, Y0, X0, BH[1], BL[1]);

        CP_WAIT0();          // W(k) copies landed (this thread's)
        __syncthreads();     // W(k) visible to all; W(s^1) free

        // launch W(k+1) into the now-free W buffer
        if (k < 8) {
            uint32_t wdst = smb + OFF_W + (s ^ 1) * 16384;
            const uint4* wh = g_wh + (k + 1) * 512;
            const uint4* wl = g_wl + (k + 1) * 512;
            cpasync16(wdst +         (t << 4), wh + t);
            cpasync16(wdst + 4096  + (t << 4), wh + 256 + t);
            cpasync16(wdst + 8192  + (t << 4), wl + t);
            cpasync16(wdst + 12288 + (t << 4), wl + 256 + t);
            CP_COMMIT();
        }

        // ---- MMA(k): 96 HMMA per warp (hh + hl + lh), W via ldsm ----
        {
            uint32_t Wb = smb + OFF_W + s * 16384;
#pragma unroll
            for (int kt = 0; kt < 4; ++kt) {
                uint32_t ksw = (uint32_t)(((kt * 2 + a_kbit) ^ lane7) << 4);
#pragma unroll
                for (int mt = 0; mt < 4; ++mt) {
                    uint32_t ah[4], al[4];
                    uint32_t aa = Wb + (((uint32_t)(mt * 16 + a_row0)) << 7) + ksw;
                    ldsm4(ah, aa);
                    ldsm4(al, aa + 8192);
                    mma2(acc[mt][0], ah, BH[0][kt * 2], BH[0][kt * 2 + 1]);
                    mma2(acc[mt][1], ah, BH[1][kt * 2], BH[1][kt * 2 + 1]);
                    mma2(acc[mt][0], ah, BL[0][kt * 2], BL[0][kt * 2 + 1]);
                    mma2(acc[mt][1], ah, BL[1][kt * 2], BL[1][kt * 2 + 1]);
                    mma2(acc[mt][0], al, BH[0][kt * 2], BH[0][kt * 2 + 1]);
                    mma2(acc[mt][1], al, BH[1][kt * 2], BH[1][kt * 2 + 1]);
                }
            }
        }

        oy[0] = noy[0]; ox[0] = nox[0];
        oy[1] = noy[1]; ox[1] = nox[1];
    }

    // ---- epilogue: bias + float2 stores (acc is warp-local; no sync) ----
    {
        const float* sbias = (const float*)(smc + OFF_BIAS);
        int tg  = lane >> 2;
        int tc2 = (lane & 3) << 1;
#pragma unroll
        for (int mt = 0; mt < 4; ++mt) {
            int c0 = mt * 16 + tg;
            int c1 = c0 + 8;
            float b0 = sbias[c0], b1 = sbias[c1];
#pragma unroll
            for (int nt = 0; nt < 2; ++nt) {
                int pix = ((gy0 + nt) << 8) + X0 + tc2;
                *reinterpret_cast<float2*>(&out[(c0 << 16) + pix]) =
                    make_float2(acc[mt][nt][0] + b0, acc[mt][nt][1] + b0);
                *reinterpret_cast<float2*>(&out[(c1 << 16) + pix]) =
                    make_float2(acc[mt][nt][2] + b1, acc[mt][nt][3] + b1);
            }
        }
    }
}

// ============================================================
// Launch
// ============================================================
extern "C" void kernel_launch(void* const* d_in, const int* in_sizes, int n_in,
                              void* d_out, int out_size) {
    const float* x      = nullptr;
    const float* offset = nullptr;
    const float* weight = nullptr;
    const float* bias   = nullptr;

    for (int i = 0; i < n_in; ++i) {
        switch (in_sizes[i]) {
            case 64 * 256 * 256: x      = (const float*)d_in[i]; break;
            case 18 * 256 * 256: offset = (const float*)d_in[i]; break;
            case 64 * 64 * 9:    weight = (const float*)d_in[i]; break;
            case 64:             bias   = (const float*)d_in[i]; break;
            default: break;
        }
    }
    if (!x || !offset || !weight || !bias) {
        x      = (const float*)d_in[0];
        offset = (const float*)d_in[1];
        weight = (const float*)d_in[2];
        bias   = (const float*)d_in[3];
    }

    cudaFuncSetAttribute(deform_main_kernel,
                         cudaFuncAttributeMaxDynamicSharedMemorySize, SMEM_TOTAL);

    prep_kernel<<<(IMG_H * IMG_W) / 64, 256>>>(x, weight);
    deform_main_kernel<<<dim3(IMG_W / 8, IMG_H / 16), 256, SMEM_TOTAL>>>(
        offset, bias, (float*)d_out);
}

// round 11
// speedup vs baseline: 1.0651x; 1.0407x over previous
#include <cuda_runtime.h>
#include <cuda_bf16.h>
#include <cstdint>

// Problem constants: B=1, CIN=COUT=64, H=W=256, K=3, stride=1, pad=1.
#define IMG_H 256
#define IMG_W 256

// ---- device scratch (no allocation allowed) ----
// g_xT: x as (y, x, c') fp32 with channels PERMUTED per 16-group so that
// storage chunk (4kt + c) holds true channels {2c, 2c+1, 2c+8, 2c+9} + 16kt
// (exactly one HMMA B-fragment quad per 16B chunk).
__device__ float g_xT[IMG_H * IMG_W * 64];
__device__ uint4 g_wh[9 * 512];   // per-tap W tile [cout=64][cin=64] bf16, SW128-preswizzled, hi
__device__ uint4 g_wl[9 * 512];   // ... lo

typedef unsigned long long u64;

// ---- packed fp32x2 helpers ----
__device__ __forceinline__ u64 fma2(u64 a, u64 b, u64 c) {
    u64 d; asm("fma.rn.f32x2 %0, %1, %2, %3;" : "=l"(d) : "l"(a), "l"(b), "l"(c));
    return d;
}
__device__ __forceinline__ u64 mul2(u64 a, u64 b) {
    u64 d; asm("mul.rn.f32x2 %0, %1, %2;" : "=l"(d) : "l"(a), "l"(b));
    return d;
}
__device__ __forceinline__ u64 splat2(float x) {
    unsigned r = __float_as_uint(x);
    u64 d; asm("mov.b64 %0, {%1, %2};" : "=l"(d) : "r"(r), "r"(r));
    return d;
}
__device__ __forceinline__ float2 unpack2(u64 v) {
    unsigned lo, hi;
    asm("mov.b64 {%0, %1}, %2;" : "=r"(lo), "=r"(hi) : "l"(v));
    return make_float2(__uint_as_float(lo), __uint_as_float(hi));
}

// ---- tensor-core + async-copy helpers (sm_80 path; compiles for compute_100) ----
__device__ __forceinline__ uint32_t smem_u32_of(const void* p) {
    uint32_t a;
    asm("{ .reg .u64 t; cvta.to.shared.u64 t, %1; cvt.u32.u64 %0, t; }"
        : "=r"(a) : "l"(p));
    return a;
}
__device__ __forceinline__ void ldsm4(uint32_t* r, uint32_t addr) {
    asm volatile("ldmatrix.sync.aligned.m8n8.x4.shared.b16 {%0,%1,%2,%3}, [%4];"
        : "=r"(r[0]), "=r"(r[1]), "=r"(r[2]), "=r"(r[3]) : "r"(addr));
}
__device__ __forceinline__ void mma2(float* c, const uint32_t* a,
                                     uint32_t b0, uint32_t b1) {
    asm volatile(
        "mma.sync.aligned.m16n8k16.row.col.f32.bf16.bf16.f32 "
        "{%0,%1,%2,%3}, {%4,%5,%6,%7}, {%8,%9}, {%0,%1,%2,%3};"
        : "+f"(c[0]), "+f"(c[1]), "+f"(c[2]), "+f"(c[3])
        : "r"(a[0]), "r"(a[1]), "r"(a[2]), "r"(a[3]), "r"(b0), "r"(b1));
}
__device__ __forceinline__ void cpasync16(uint32_t dst, const void* src) {
    asm volatile("cp.async.cg.shared.global [%0], [%1], 16;" :: "r"(dst), "l"(src));
}
#define CP_COMMIT() asm volatile("cp.async.commit_group;" ::: "memory")
#define CP_WAIT0()  asm volatile("cp.async.wait_group 0;" ::: "memory")

// ---- smem layout (bytes from dynamic base) ----
#define OFF_BIAS   0          // 64 floats
#define OFF_TILE   1024       // halo fp32: 19*11*64*4 = 53504
#define OFF_W      54528      // W bufs: 2 x (hi 8192 + lo 8192) = 32768
#define SMEM_TOTAL 87296

// ============================================================
// Kernel 1: transpose x (C,H,W)->(H,W,C')  +  weight split/relayout.
//   C' = fragment-permuted channel order (see g_xT comment).
// ============================================================
__global__ void prep_kernel(const float* __restrict__ x,
                            const float* __restrict__ wsrc) {
    __shared__ float ts[64][65];
    const int t = threadIdx.x;

    // weight prep: first 144 blocks handle 256 weights each (64*64*9 = 36864)
    if (blockIdx.x < 144) {
        int idx  = blockIdx.x * 256 + t;
        int cout = idx / 576;
        int r    = idx - cout * 576;
        int cin  = r / 9;
        int k    = r - cin * 9;
        float v  = wsrc[idx];
        __nv_bfloat16 hb = __float2bfloat16(v);
        float hv = __bfloat162float(hb);
        __nv_bfloat16 lb = __float2bfloat16(v - hv);
        uint32_t off = (cout << 7) + (cin << 1);
        uint32_t sw  = off ^ ((off >> 3) & 0x70);
        ((__nv_bfloat16*)g_wh)[k * 4096 + (sw >> 1)] = hb;
        ((__nv_bfloat16*)g_wl)[k * 4096 + (sw >> 1)] = lb;
    }

    // transpose with channel permutation:
    // true channel tx -> slot ((j&7)>>1)*4 + ((j>>3)<<1) + (j&1), j = tx&15
    const int tx = t & 63;
    const int ty = t >> 6;
    const int P0 = blockIdx.x * 64;
    const int j    = tx & 15;
    const int slot = (((j & 7) >> 1) << 2) + ((j >> 3) << 1) + (j & 1);
    const int ptx  = (tx & ~15) | slot;
#pragma unroll
    for (int i = 0; i < 16; ++i) {
        int cch = (i << 2) + ty;
        ts[cch][tx] = x[cch * (IMG_H * IMG_W) + P0 + tx];
    }
    __syncthreads();
#pragma unroll
    for (int i = 0; i < 16; ++i) {
        int p = (i << 2) + ty;
        g_xT[(P0 + p) * 64 + ptx] = ts[tx][p];
    }
}

// ============================================================
// Sample one pixel's 16 fragment channels straight into B-fragment
// registers. One LDS.128 per (corner, kt): chunk (4kt+c) holds exactly
// this lane's quad {2c,2c+1 | 2c+8,2c+9}+16kt (lo u64 -> b0, hi u64 -> b1).
// ============================================================
__device__ __forceinline__ void sample_px(
    const char* __restrict__ tileb, int c, int ky, int kx,
    float offy, float offx, int gy, int gx, int Y0, int X0,
    uint32_t* BH, uint32_t* BL)
{
    float pyf = (float)(gy - 1 + ky) + offy;
    float pxf = (float)(gx - 1 + kx) + offx;
    float y0f = floorf(pyf), x0f = floorf(pxf);
    int   y0  = (int)y0f,   x0  = (int)x0f;
    float wy1 = pyf - y0f,  wx1 = pxf - x0f;
    float wy0 = 1.f - wy1,  wx0 = 1.f - wx1;
    int iy = y0 - (Y0 - 1);
    int ix = x0 - (X0 - 1);
    float fy0 = ((unsigned)y0       < 256u && (unsigned)iy       <= 17u) ? 1.f : 0.f;
    float fy1 = ((unsigned)(y0 + 1) < 256u && (unsigned)(iy + 1) <= 18u) ? 1.f : 0.f;
    float fx0 = ((unsigned)x0       < 256u && (unsigned)ix       <=  9u) ? 1.f : 0.f;
    float fx1 = ((unsigned)(x0 + 1) < 256u && (unsigned)(ix + 1) <= 10u) ? 1.f : 0.f;
    u64 W00 = splat2(wy0 * wx0 * fy0 * fx0);
    u64 W01 = splat2(wy0 * wx1 * fy0 * fx1);
    u64 W10 = splat2(wy1 * wx0 * fy1 * fx0);
    u64 W11 = splat2(wy1 * wx1 * fy1 * fx1);
    int iyc = min(max(iy, 0), 17);
    int ixc = min(max(ix, 0), 9);
    int c00 = iyc * 11 + ixc;
    int c01 = c00 + 1;
    int c10 = c00 + 11;
    int c11 = c00 + 12;
    // corner base = cell*256 + ((c ^ (s&3))<<4); per-kt offset = (kt<<6) ^ ((s&4)<<4)
    const char* p00 = tileb + (c00 << 8) + ((c ^ (c00 & 3)) << 4);
    const char* p01 = tileb + (c01 << 8) + ((c ^ (c01 & 3)) << 4);
    const char* p10 = tileb + (c10 << 8) + ((c ^ (c10 & 3)) << 4);
    const char* p11 = tileb + (c11 << 8) + ((c ^ (c11 & 3)) << 4);
    const uint32_t b00 = (uint32_t)((c00 & 4) << 4);
    const uint32_t b01 = (uint32_t)((c01 & 4) << 4);
    const uint32_t b10 = (uint32_t)((c10 & 4) << 4);
    const uint32_t b11 = (uint32_t)((c11 & 4) << 4);
#pragma unroll
    for (int kt = 0; kt < 4; ++kt) {
        const uint32_t ko = (uint32_t)(kt << 6);
        ulonglong2 v00 = *(const ulonglong2*)(p00 + (ko ^ b00));
        ulonglong2 v01 = *(const ulonglong2*)(p01 + (ko ^ b01));
        ulonglong2 v10 = *(const ulonglong2*)(p10 + (ko ^ b10));
        ulonglong2 v11 = *(const ulonglong2*)(p11 + (ko ^ b11));
        u64 lo = fma2(v00.x, W00, fma2(v01.x, W01, fma2(v10.x, W10, mul2(v11.x, W11))));
        u64 hi = fma2(v00.y, W00, fma2(v01.y, W01, fma2(v10.y, W10, mul2(v11.y, W11))));
        float2 f0 = unpack2(lo);   // true ch 2c, 2c+1   -> b0
        float2 f1 = unpack2(hi);   // true ch 2c+8, 2c+9 -> b1
        uint32_t h0, h1, l0, l1;
        asm("cvt.rn.satfinite.bf16x2.f32 %0, %1, %2;" : "=r"(h0) : "f"(f0.y), "f"(f0.x));
        asm("cvt.rn.satfinite.bf16x2.f32 %0, %1, %2;" : "=r"(h1) : "f"(f1.y), "f"(f1.x));
        float r0 = f0.x - __uint_as_float(h0 << 16);
        float r1 = f0.y - __uint_as_float(h0 & 0xffff0000u);
        float r2 = f1.x - __uint_as_float(h1 << 16);
        float r3 = f1.y - __uint_as_float(h1 & 0xffff0000u);
        asm("cvt.rn.satfinite.bf16x2.f32 %0, %1, %2;" : "=r"(l0) : "f"(r1), "f"(r0));
        asm("cvt.rn.satfinite.bf16x2.f32 %0, %1, %2;" : "=r"(l1) : "f"(r3), "f"(r2));
        BH[kt * 2]     = h0;
        BH[kt * 2 + 1] = h1;
        BL[kt * 2]     = l0;
        BL[kt * 2 + 1] = l1;
    }
}

// ============================================================
// Kernel 2: main — 16x8 px tile, 256 threads (8 warps), 2 blocks/SM.
//   Warp = 64 cout x 16 px (2 n-tiles). Samples go straight into
//   B-fragment registers. W double-buffered (cp.async).
//   One __syncthreads per tap (W buffer handoff only).
// ============================================================
extern __shared__ char smc[];

__global__ __launch_bounds__(256, 2)
void deform_main_kernel(const float* __restrict__ offs,
                        const float* __restrict__ bias,
                        float* __restrict__ out) {
    const char* tileb = smc + OFF_TILE;
    float* tilef = (float*)(smc + OFF_TILE);
    const uint32_t smb = smem_u32_of(smc);

    const int t    = threadIdx.x;
    const int lane = t & 31;
    const int wid  = t >> 5;
    const int X0   = blockIdx.x << 3;      // 8 wide
    const int Y0   = blockIdx.y << 4;      // 16 tall

    if (t < 64) ((float*)(smc + OFF_BIAS))[t] = bias[t];

    // fragment/sampling identity: quad of lanes per pixel
    const int c    = lane & 3;             // channel group
    const int gx   = X0 + (lane >> 2);     // 0..7
    const int gy0  = Y0 + (wid << 1);      // rows wid*2 (nt=0), +1 (nt=1)
    const int pix0 = (gy0 << 8) + gx;
    const int pix1 = pix0 + 256;

    // tap-0 offsets
    float oy[2], ox[2];
    oy[0] = offs[pix0];  ox[0] = offs[(1 << 16) + pix0];
    oy[1] = offs[pix1];  ox[1] = offs[(1 << 16) + pix1];

    // ---- halo tile: 19x11 cells x 64 ch fp32 (zero outside image) ----
    // (16B chunk copies; channel permutation already applied in g_xT)
    for (int f = t; f < 209 * 16; f += 256) {
        int cell = f >> 4;
        int q    = f & 15;
        int rr   = cell / 11;
        int cc   = cell - rr * 11;
        int hy   = Y0 - 1 + rr;
        int hx   = X0 - 1 + cc;
        float4 v = make_float4(0.f, 0.f, 0.f, 0.f);
        if ((unsigned)hy < (unsigned)IMG_H && (unsigned)hx < (unsigned)IMG_W)
            v = *reinterpret_cast<const float4*>(
                    &g_xT[(((hy << 8) + hx) << 6) + (q << 2)]);
        *reinterpret_cast<float4*>(
            &tilef[(cell << 6) + ((q ^ (cell & 7)) << 2)]) = v;
    }

    // ---- W0 async copy ----
    {
        uint32_t wdst = smb + OFF_W;
        cpasync16(wdst +         (t << 4), g_wh + t);
        cpasync16(wdst + 4096  + (t << 4), g_wh + 256 + t);
        cpasync16(wdst + 8192  + (t << 4), g_wl + t);
        cpasync16(wdst + 12288 + (t << 4), g_wl + 256 + t);
        CP_COMMIT();
    }
    __syncthreads();     // halo visible (W0 waited inside loop)

    // mma W-operand identity (A operand = weights, m = cout)
    const int lane7  = lane & 7;
    const int a_row0 = (lane & 7) + (lane & 8);
    const int a_kbit = lane >> 4;

    float acc[4][2][4];
#pragma unroll
    for (int m = 0; m < 4; ++m)
#pragma unroll
        for (int n = 0; n < 2; ++n)
#pragma unroll
            for (int j = 0; j < 4; ++j) acc[m][n][j] = 0.f;

    uint32_t BH[2][8], BL[2][8];

#pragma unroll 1
    for (int k = 0; k < 9; ++k) {
        const int s  = k & 1;
        const int ky = k / 3;
        const int kx = k - ky * 3;

        // prefetch offsets for tap k+1
        float noy[2], nox[2];
        if (k < 8) {
            noy[0] = offs[(((k + 1) * 2    ) << 16) + pix0];
            nox[0] = offs[(((k + 1) * 2 + 1) << 16) + pix0];
            noy[1] = offs[(((k + 1) * 2    ) << 16) + pix1];
            nox[1] = offs[(((k + 1) * 2 + 1) << 16) + pix1];
        }

        // ---- sample tap k into B-fragment registers (halo only; no sync) ----
        sample_px(tileb, c, ky, kx, oy[0], ox[0], gy0,     gx, Y0, X0, BH[0], BL[0]);
        sample_px(tileb, c, ky, kx, oy[1], ox[1], gy0 + 1, gx, Y0, X0, BH[1], BL[1]);

        CP_WAIT0();          // W(k) copies landed (this thread's)
        __syncthreads();     // W(k) visible to all; W(s^1) free

        // launch W(k+1) into the now-free W buffer
        if (k < 8) {
            uint32_t wdst = smb + OFF_W + (s ^ 1) * 16384;
            const uint4* wh = g_wh + (k + 1) * 512;
            const uint4* wl = g_wl + (k + 1) * 512;
            cpasync16(wdst +         (t << 4), wh + t);
            cpasync16(wdst + 4096  + (t << 4), wh + 256 + t);
            cpasync16(wdst + 8192  + (t << 4), wl + t);
            cpasync16(wdst + 12288 + (t << 4), wl + 256 + t);
            CP_COMMIT();
        }

        // ---- MMA(k): 96 HMMA per warp (hh + hl + lh), W via ldsm ----
        {
            uint32_t Wb = smb + OFF_W + s * 16384;
#pragma unroll
            for (int kt = 0; kt < 4; ++kt) {
                uint32_t ksw = (uint32_t)(((kt * 2 + a_kbit) ^ lane7) << 4);
#pragma unroll
                for (int mt = 0; mt < 4; ++mt) {
                    uint32_t ah[4], al[4];
                    uint32_t aa = Wb + (((uint32_t)(mt * 16 + a_row0)) << 7) + ksw;
                    ldsm4(ah, aa);
                    ldsm4(al, aa + 8192);
                    mma2(acc[mt][0], ah, BH[0][kt * 2], BH[0][kt * 2 + 1]);
                    mma2(acc[mt][1], ah, BH[1][kt * 2], BH[1][kt * 2 + 1]);
                    mma2(acc[mt][0], ah, BL[0][kt * 2], BL[0][kt * 2 + 1]);
                    mma2(acc[mt][1], ah, BL[1][kt * 2], BL[1][kt * 2 + 1]);
                    mma2(acc[mt][0], al, BH[0][kt * 2], BH[0][kt * 2 + 1]);
                    mma2(acc[mt][1], al, BH[1][kt * 2], BH[1][kt * 2 + 1]);
                }
            }
        }

        oy[0] = noy[0]; ox[0] = nox[0];
        oy[1] = noy[1]; ox[1] = nox[1];
    }

    // ---- epilogue: bias + float2 stores (acc is warp-local; no sync) ----
    {
        const float* sbias = (const float*)(smc + OFF_BIAS);
        int tg  = lane >> 2;
        int tc2 = (lane & 3) << 1;
#pragma unroll
        for (int mt = 0; mt < 4; ++mt) {
            int c0 = mt * 16 + tg;
            int c1 = c0 + 8;
            float b0 = sbias[c0], b1 = sbias[c1];
#pragma unroll
            for (int nt = 0; nt < 2; ++nt) {
                int pix = ((gy0 + nt) << 8) + X0 + tc2;
                *reinterpret_cast<float2*>(&out[(c0 << 16) + pix]) =
                    make_float2(acc[mt][nt][0] + b0, acc[mt][nt][1] + b0);
                *reinterpret_cast<float2*>(&out[(c1 << 16) + pix]) =
                    make_float2(acc[mt][nt][2] + b1, acc[mt][nt][3] + b1);
            }
        }
    }
}

// ============================================================
// Launch
// ============================================================
extern "C" void kernel_launch(void* const* d_in, const int* in_sizes, int n_in,
                              void* d_out, int out_size) {
    const float* x      = nullptr;
    const float* offset = nullptr;
    const float* weight = nullptr;
    const float* bias   = nullptr;

    for (int i = 0; i < n_in; ++i) {
        switch (in_sizes[i]) {
            case 64 * 256 * 256: x      = (const float*)d_in[i]; break;
            case 18 * 256 * 256: offset = (const float*)d_in[i]; break;
            case 64 * 64 * 9:    weight = (const float*)d_in[i]; break;
            case 64:             bias   = (const float*)d_in[i]; break;
            default: break;
        }
    }
    if (!x || !offset || !weight || !bias) {
        x      = (const float*)d_in[0];
        offset = (const float*)d_in[1];
        weight = (const float*)d_in[2];
        bias   = (const float*)d_in[3];
    }

    cudaFuncSetAttribute(deform_main_kernel,
                         cudaFuncAttributeMaxDynamicSharedMemorySize, SMEM_TOTAL);

    prep_kernel<<<(IMG_H * IMG_W) / 64, 256>>>(x, weight);
    deform_main_kernel<<<dim3(IMG_W / 8, IMG_H / 16), 256, SMEM_TOTAL>>>(
        offset, bias, (float*)d_out);
}

// round 12
// speedup vs baseline: 1.1533x; 1.0829x over previous
#include <cuda_runtime.h>
#include <cuda_bf16.h>
#include <cstdint>

// Problem constants: B=1, CIN=COUT=64, H=W=256, K=3, stride=1, pad=1.
#define IMG_H 256
#define IMG_W 256

// ---- device scratch (no allocation allowed) ----
// g_xT: x as (y, x, c') fp32 with channels PERMUTED per 16-group so that
// storage chunk (4kt + c) holds true channels {2c, 2c+1, 2c+8, 2c+9} + 16kt
// (exactly one HMMA B-fragment quad per 16B chunk).
__device__ float g_xT[IMG_H * IMG_W * 64];
// W in MMA A-fragment-linear layout: [tap][kt*4+mt][lane] -> uint4 {a0,a1,a2,a3}
// per PTX m16n8k16 A row-major spec (g = lane>>2, tg = lane&3):
//   a0 = W[mt*16+g   ][kt*16+tg*2 .. +1]
//   a1 = W[mt*16+g+8 ][kt*16+tg*2 .. +1]
//   a2 = W[mt*16+g   ][kt*16+tg*2+8 .. +9]
//   a3 = W[mt*16+g+8 ][kt*16+tg*2+8 .. +9]
__device__ uint4 g_wfh[9 * 16 * 32];   // hi bf16 fragments
__device__ uint4 g_wfl[9 * 16 * 32];   // lo bf16 fragments

typedef unsigned long long u64;

// ---- packed fp32x2 helpers ----
__device__ __forceinline__ u64 fma2(u64 a, u64 b, u64 c) {
    u64 d; asm("fma.rn.f32x2 %0, %1, %2, %3;" : "=l"(d) : "l"(a), "l"(b), "l"(c));
    return d;
}
__device__ __forceinline__ u64 mul2(u64 a, u64 b) {
    u64 d; asm("mul.rn.f32x2 %0, %1, %2;" : "=l"(d) : "l"(a), "l"(b));
    return d;
}
__device__ __forceinline__ u64 splat2(float x) {
    unsigned r = __float_as_uint(x);
    u64 d; asm("mov.b64 %0, {%1, %2};" : "=l"(d) : "r"(r), "r"(r));
    return d;
}
__device__ __forceinline__ float2 unpack2(u64 v) {
    unsigned lo, hi;
    asm("mov.b64 {%0, %1}, %2;" : "=r"(lo), "=r"(hi) : "l"(v));
    return make_float2(__uint_as_float(lo), __uint_as_float(hi));
}

// ---- tensor-core helpers (sm_80 path; compiles for compute_100) ----
__device__ __forceinline__ void mma2(float* c, const uint32_t* a,
                                     uint32_t b0, uint32_t b1) {
    asm volatile(
        "mma.sync.aligned.m16n8k16.row.col.f32.bf16.bf16.f32 "
        "{%0,%1,%2,%3}, {%4,%5,%6,%7}, {%8,%9}, {%0,%1,%2,%3};"
        : "+f"(c[0]), "+f"(c[1]), "+f"(c[2]), "+f"(c[3])
        : "r"(a[0]), "r"(a[1]), "r"(a[2]), "r"(a[3]), "r"(b0), "r"(b1));
}

// ---- smem layout (bytes from dynamic base) ----
#define OFF_BIAS   0          // 64 floats
#define OFF_TILE   1024       // halo fp32: 19*11*64*4 = 53504
#define SMEM_TOTAL 54528

// ============================================================
// Kernel 1: transpose x (C,H,W)->(H,W,C')  +  W fragment prep.
// ============================================================
__global__ void prep_kernel(const float* __restrict__ x,
                            const float* __restrict__ wsrc) {
    __shared__ float ts[64][65];
    const int t = threadIdx.x;

    // W fragment prep: first 18 blocks handle 4608 fragment slots
    if (blockIdx.x < 18) {
        int idx  = blockIdx.x * 256 + t;       // ((k*16)+(kt*4+mt))*32 + lane
        int lane = idx & 31;
        int fm   = (idx >> 5) & 15;
        int k    = idx >> 9;                   // 0..8
        int kt   = fm >> 2;
        int mt   = fm & 3;
        int g    = lane >> 2;
        int tg   = lane & 3;
        int r0   = mt * 16 + g;
        int r1   = r0 + 8;
        int cc0  = kt * 16 + tg * 2;

        uint32_t ah[4], al[4];
        const int rows[4] = {r0, r1, r0, r1};
        const int cols[4] = {cc0, cc0, cc0 + 8, cc0 + 8};
#pragma unroll
        for (int i = 0; i < 4; ++i) {
            float v0 = wsrc[rows[i] * 576 + (cols[i]    ) * 9 + k];
            float v1 = wsrc[rows[i] * 576 + (cols[i] + 1) * 9 + k];
            __nv_bfloat16 h0 = __float2bfloat16(v0);
            __nv_bfloat16 h1 = __float2bfloat16(v1);
            __nv_bfloat16 l0 = __float2bfloat16(v0 - __bfloat162float(h0));
            __nv_bfloat16 l1 = __float2bfloat16(v1 - __bfloat162float(h1));
            uint32_t h0b = (uint32_t)*(uint16_t*)&h0;
            uint32_t h1b = (uint32_t)*(uint16_t*)&h1;
            uint32_t l0b = (uint32_t)*(uint16_t*)&l0;
            uint32_t l1b = (uint32_t)*(uint16_t*)&l1;
            ah[i] = h0b | (h1b << 16);
            al[i] = l0b | (l1b << 16);
        }
        g_wfh[idx] = make_uint4(ah[0], ah[1], ah[2], ah[3]);
        g_wfl[idx] = make_uint4(al[0], al[1], al[2], al[3]);
    }

    // transpose with channel permutation:
    // true channel tx -> slot ((j&7)>>1)*4 + ((j>>3)<<1) + (j&1), j = tx&15
    const int tx = t & 63;
    const int ty = t >> 6;
    const int P0 = blockIdx.x * 64;
    const int j    = tx & 15;
    const int slot = (((j & 7) >> 1) << 2) + ((j >> 3) << 1) + (j & 1);
    const int ptx  = (tx & ~15) | slot;
#pragma unroll
    for (int i = 0; i < 16; ++i) {
        int cch = (i << 2) + ty;
        ts[cch][tx] = x[cch * (IMG_H * IMG_W) + P0 + tx];
    }
    __syncthreads();
#pragma unroll
    for (int i = 0; i < 16; ++i) {
        int p = (i << 2) + ty;
        g_xT[(P0 + p) * 64 + ptx] = ts[tx][p];
    }
}

// ============================================================
// Sample one pixel's 16 fragment channels straight into B-fragment
// registers. One LDS.128 per (corner, kt).
// ============================================================
__device__ __forceinline__ void sample_px(
    const char* __restrict__ tileb, int c, int ky, int kx,
    float offy, float offx, int gy, int gx, int Y0, int X0,
    uint32_t* BH, uint32_t* BL)
{
    float pyf = (float)(gy - 1 + ky) + offy;
    float pxf = (float)(gx - 1 + kx) + offx;
    float y0f = floorf(pyf), x0f = floorf(pxf);
    int   y0  = (int)y0f,   x0  = (int)x0f;
    float wy1 = pyf - y0f,  wx1 = pxf - x0f;
    float wy0 = 1.f - wy1,  wx0 = 1.f - wx1;
    int iy = y0 - (Y0 - 1);
    int ix = x0 - (X0 - 1);
    float fy0 = ((unsigned)y0       < 256u && (unsigned)iy       <= 17u) ? 1.f : 0.f;
    float fy1 = ((unsigned)(y0 + 1) < 256u && (unsigned)(iy + 1) <= 18u) ? 1.f : 0.f;
    float fx0 = ((unsigned)x0       < 256u && (unsigned)ix       <=  9u) ? 1.f : 0.f;
    float fx1 = ((unsigned)(x0 + 1) < 256u && (unsigned)(ix + 1) <= 10u) ? 1.f : 0.f;
    u64 W00 = splat2(wy0 * wx0 * fy0 * fx0);
    u64 W01 = splat2(wy0 * wx1 * fy0 * fx1);
    u64 W10 = splat2(wy1 * wx0 * fy1 * fx0);
    u64 W11 = splat2(wy1 * wx1 * fy1 * fx1);
    int iyc = min(max(iy, 0), 17);
    int ixc = min(max(ix, 0), 9);
    int c00 = iyc * 11 + ixc;
    int c01 = c00 + 1;
    int c10 = c00 + 11;
    int c11 = c00 + 12;
    const char* p00 = tileb + (c00 << 8) + ((c ^ (c00 & 3)) << 4);
    const char* p01 = tileb + (c01 << 8) + ((c ^ (c01 & 3)) << 4);
    const char* p10 = tileb + (c10 << 8) + ((c ^ (c10 & 3)) << 4);
    const char* p11 = tileb + (c11 << 8) + ((c ^ (c11 & 3)) << 4);
    const uint32_t b00 = (uint32_t)((c00 & 4) << 4);
    const uint32_t b01 = (uint32_t)((c01 & 4) << 4);
    const uint32_t b10 = (uint32_t)((c10 & 4) << 4);
    const uint32_t b11 = (uint32_t)((c11 & 4) << 4);
#pragma unroll
    for (int kt = 0; kt < 4; ++kt) {
        const uint32_t ko = (uint32_t)(kt << 6);
        ulonglong2 v00 = *(const ulonglong2*)(p00 + (ko ^ b00));
        ulonglong2 v01 = *(const ulonglong2*)(p01 + (ko ^ b01));
        ulonglong2 v10 = *(const ulonglong2*)(p10 + (ko ^ b10));
        ulonglong2 v11 = *(const ulonglong2*)(p11 + (ko ^ b11));
        u64 lo = fma2(v00.x, W00, fma2(v01.x, W01, fma2(v10.x, W10, mul2(v11.x, W11))));
        u64 hi = fma2(v00.y, W00, fma2(v01.y, W01, fma2(v10.y, W10, mul2(v11.y, W11))));
        float2 f0 = unpack2(lo);   // true ch 2c, 2c+1   -> b0
        float2 f1 = unpack2(hi);   // true ch 2c+8, 2c+9 -> b1
        uint32_t h0, h1, l0, l1;
        asm("cvt.rn.satfinite.bf16x2.f32 %0, %1, %2;" : "=r"(h0) : "f"(f0.y), "f"(f0.x));
        asm("cvt.rn.satfinite.bf16x2.f32 %0, %1, %2;" : "=r"(h1) : "f"(f1.y), "f"(f1.x));
        float r0 = f0.x - __uint_as_float(h0 << 16);
        float r1 = f0.y - __uint_as_float(h0 & 0xffff0000u);
        float r2 = f1.x - __uint_as_float(h1 << 16);
        float r3 = f1.y - __uint_as_float(h1 & 0xffff0000u);
        asm("cvt.rn.satfinite.bf16x2.f32 %0, %1, %2;" : "=r"(l0) : "f"(r1), "f"(r0));
        asm("cvt.rn.satfinite.bf16x2.f32 %0, %1, %2;" : "=r"(l1) : "f"(r3), "f"(r2));
        BH[kt * 2]     = h0;
        BH[kt * 2 + 1] = h1;
        BL[kt * 2]     = l0;
        BL[kt * 2 + 1] = l1;
    }
}

// ============================================================
// Kernel 2: main — 16x8 px tile, 256 threads (8 warps), 2 blocks/SM.
//   Warp = 64 cout x 16 px. Samples -> B-fragment registers; W fragments
//   LDG'd per warp from fragment-linear global (L1/L2 resident).
//   ZERO block-wide syncs in the tap loop.
// ============================================================
extern __shared__ char smc[];

__global__ __launch_bounds__(256, 2)
void deform_main_kernel(const float* __restrict__ offs,
                        const float* __restrict__ bias,
                        float* __restrict__ out) {
    const char* tileb = smc + OFF_TILE;
    float* tilef = (float*)(smc + OFF_TILE);

    const int t    = threadIdx.x;
    const int lane = t & 31;
    const int wid  = t >> 5;
    const int X0   = blockIdx.x << 3;      // 8 wide
    const int Y0   = blockIdx.y << 4;      // 16 tall

    if (t < 64) ((float*)(smc + OFF_BIAS))[t] = bias[t];

    // fragment/sampling identity: quad of lanes per pixel
    const int c    = lane & 3;             // channel group
    const int gx   = X0 + (lane >> 2);     // 0..7
    const int gy0  = Y0 + (wid << 1);      // rows wid*2 (nt=0), +1 (nt=1)
    const int pix0 = (gy0 << 8) + gx;
    const int pix1 = pix0 + 256;

    // tap-0 offsets
    float oy[2], ox[2];
    oy[0] = offs[pix0];  ox[0] = offs[(1 << 16) + pix0];
    oy[1] = offs[pix1];  ox[1] = offs[(1 << 16) + pix1];

    // ---- halo tile: 19x11 cells x 64 ch fp32 (zero outside image) ----
    for (int f = t; f < 209 * 16; f += 256) {
        int cell = f >> 4;
        int q    = f & 15;
        int rr   = cell / 11;
        int cc   = cell - rr * 11;
        int hy   = Y0 - 1 + rr;
        int hx   = X0 - 1 + cc;
        float4 v = make_float4(0.f, 0.f, 0.f, 0.f);
        if ((unsigned)hy < (unsigned)IMG_H && (unsigned)hx < (unsigned)IMG_W)
            v = *reinterpret_cast<const float4*>(
                    &g_xT[(((hy << 8) + hx) << 6) + (q << 2)]);
        *reinterpret_cast<float4*>(
            &tilef[(cell << 6) + ((q ^ (cell & 7)) << 2)]) = v;
    }
    __syncthreads();     // halo + bias visible — the ONLY block-wide sync

    float acc[4][2][4];
#pragma unroll
    for (int m = 0; m < 4; ++m)
#pragma unroll
        for (int n = 0; n < 2; ++n)
#pragma unroll
            for (int j = 0; j < 4; ++j) acc[m][n][j] = 0.f;

    uint32_t BH[2][8], BL[2][8];

#pragma unroll 1
    for (int k = 0; k < 9; ++k) {
        const int ky = k / 3;
        const int kx = k - ky * 3;

        // prefetch offsets for tap k+1
        float noy[2], nox[2];
        if (k < 8) {
            noy[0] = offs[(((k + 1) * 2    ) << 16) + pix0];
            nox[0] = offs[(((k + 1) * 2 + 1) << 16) + pix0];
            noy[1] = offs[(((k + 1) * 2    ) << 16) + pix1];
            nox[1] = offs[(((k + 1) * 2 + 1) << 16) + pix1];
        }

        // ---- sample tap k into B-fragment registers (halo only; no sync) ----
        sample_px(tileb, c, ky, kx, oy[0], ox[0], gy0,     gx, Y0, X0, BH[0], BL[0]);
        sample_px(tileb, c, ky, kx, oy[1], ox[1], gy0 + 1, gx, Y0, X0, BH[1], BL[1]);

        // ---- MMA(k): 96 HMMA per warp (hh + hl + lh), W frags via LDG ----
        {
            const uint4* __restrict__ wfh = g_wfh + k * 512 + lane;
            const uint4* __restrict__ wfl = g_wfl + k * 512 + lane;
#pragma unroll
            for (int kt = 0; kt < 4; ++kt) {
#pragma unroll
                for (int mt = 0; mt < 4; ++mt) {
                    uint4 AH = __ldg(wfh + ((kt << 2) | mt) * 32);
                    uint4 AL = __ldg(wfl + ((kt << 2) | mt) * 32);
                    mma2(acc[mt][0], &AH.x, BH[0][kt * 2], BH[0][kt * 2 + 1]);
                    mma2(acc[mt][1], &AH.x, BH[1][kt * 2], BH[1][kt * 2 + 1]);
                    mma2(acc[mt][0], &AH.x, BL[0][kt * 2], BL[0][kt * 2 + 1]);
                    mma2(acc[mt][1], &AH.x, BL[1][kt * 2], BL[1][kt * 2 + 1]);
                    mma2(acc[mt][0], &AL.x, BH[0][kt * 2], BH[0][kt * 2 + 1]);
                    mma2(acc[mt][1], &AL.x, BH[1][kt * 2], BH[1][kt * 2 + 1]);
                }
            }
        }

        oy[0] = noy[0]; ox[0] = nox[0];
        oy[1] = noy[1]; ox[1] = nox[1];
    }

    // ---- epilogue: bias + float2 stores (acc is warp-local; no sync) ----
    {
        const float* sbias = (const float*)(smc + OFF_BIAS);
        int tg  = lane >> 2;
        int tc2 = (lane & 3) << 1;
#pragma unroll
        for (int mt = 0; mt < 4; ++mt) {
            int c0 = mt * 16 + tg;
            int c1 = c0 + 8;
            float b0 = sbias[c0], b1 = sbias[c1];
#pragma unroll
            for (int nt = 0; nt < 2; ++nt) {
                int pix = ((gy0 + nt) << 8) + X0 + tc2;
                *reinterpret_cast<float2*>(&out[(c0 << 16) + pix]) =
                    make_float2(acc[mt][nt][0] + b0, acc[mt][nt][1] + b0);
                *reinterpret_cast<float2*>(&out[(c1 << 16) + pix]) =
                    make_float2(acc[mt][nt][2] + b1, acc[mt][nt][3] + b1);
            }
        }
    }
}

// ============================================================
// Launch
// ============================================================
extern "C" void kernel_launch(void* const* d_in, const int* in_sizes, int n_in,
                              void* d_out, int out_size) {
    const float* x      = nullptr;
    const float* offset = nullptr;
    const float* weight = nullptr;
    const float* bias   = nullptr;

    for (int i = 0; i < n_in; ++i) {
        switch (in_sizes[i]) {
            case 64 * 256 * 256: x      = (const float*)d_in[i]; break;
            case 18 * 256 * 256: offset = (const float*)d_in[i]; break;
            case 64 * 64 * 9:    weight = (const float*)d_in[i]; break;
            case 64:             bias   = (const float*)d_in[i]; break;
            default: break;
        }
    }
    if (!x || !offset || !weight || !bias) {
        x      = (const float*)d_in[0];
        offset = (const float*)d_in[1];
        weight = (const float*)d_in[2];
        bias   = (const float*)d_in[3];
    }

    cudaFuncSetAttribute(deform_main_kernel,
                         cudaFuncAttributeMaxDynamicSharedMemorySize, SMEM_TOTAL);

    prep_kernel<<<(IMG_H * IMG_W) / 64, 256>>>(x, weight);
    deform_main_kernel<<<dim3(IMG_W / 8, IMG_H / 16), 256, SMEM_TOTAL>>>(
        offset, bias, (float*)d_out);
}

// round 13
// speedup vs baseline: 1.1778x; 1.0213x over previous
#include <cuda_runtime.h>
#include <cuda_fp16.h>
#include <cstdint>

// Problem constants: B=1, CIN=COUT=64, H=W=256, K=3, stride=1, pad=1.
#define IMG_H 256
#define IMG_W 256

// ---- device scratch (no allocation allowed) ----
// g_xT: x as (y, x, c') fp32 with channels PERMUTED per 16-group so that
// storage chunk (4kt + c) holds true channels {2c, 2c+1, 2c+8, 2c+9} + 16kt
// (exactly one HMMA B-fragment quad per 16B chunk).
__device__ float g_xT[IMG_H * IMG_W * 64];
// W in MMA A-fragment-linear layout: [tap][kt*4+mt][lane] -> uint4 {a0,a1,a2,a3}
// per PTX m16n8k16 A row-major spec (g = lane>>2, tg = lane&3):
//   a0 = W[mt*16+g   ][kt*16+tg*2 .. +1]
//   a1 = W[mt*16+g+8 ][kt*16+tg*2 .. +1]
//   a2 = W[mt*16+g   ][kt*16+tg*2+8 .. +9]
//   a3 = W[mt*16+g+8 ][kt*16+tg*2+8 .. +9]
// fp16 2-term weight split: w = wh + wl (wl captures the next 11 bits).
__device__ uint4 g_wfh[9 * 16 * 32];   // hi fp16 fragments
__device__ uint4 g_wfl[9 * 16 * 32];   // lo fp16 fragments

typedef unsigned long long u64;

// ---- packed fp32x2 helpers ----
__device__ __forceinline__ u64 fma2(u64 a, u64 b, u64 c) {
    u64 d; asm("fma.rn.f32x2 %0, %1, %2, %3;" : "=l"(d) : "l"(a), "l"(b), "l"(c));
    return d;
}
__device__ __forceinline__ u64 mul2(u64 a, u64 b) {
    u64 d; asm("mul.rn.f32x2 %0, %1, %2;" : "=l"(d) : "l"(a), "l"(b));
    return d;
}
__device__ __forceinline__ u64 splat2(float x) {
    unsigned r = __float_as_uint(x);
    u64 d; asm("mov.b64 %0, {%1, %2};" : "=l"(d) : "r"(r), "r"(r));
    return d;
}
__device__ __forceinline__ float2 unpack2(u64 v) {
    unsigned lo, hi;
    asm("mov.b64 {%0, %1}, %2;" : "=r"(lo), "=r"(hi) : "l"(v));
    return make_float2(__uint_as_float(lo), __uint_as_float(hi));
}

// ---- tensor-core helpers (sm_80 path; compiles for compute_100) ----
__device__ __forceinline__ void mma2(float* c, const uint32_t* a,
                                     uint32_t b0, uint32_t b1) {
    asm volatile(
        "mma.sync.aligned.m16n8k16.row.col.f32.f16.f16.f32 "
        "{%0,%1,%2,%3}, {%4,%5,%6,%7}, {%8,%9}, {%0,%1,%2,%3};"
        : "+f"(c[0]), "+f"(c[1]), "+f"(c[2]), "+f"(c[3])
        : "r"(a[0]), "r"(a[1]), "r"(a[2]), "r"(a[3]), "r"(b0), "r"(b1));
}

// ---- smem layout (bytes from dynamic base) ----
#define OFF_BIAS   0          // 64 floats
#define OFF_TILE   1024       // halo fp32: 19*11*64*4 = 53504
#define SMEM_TOTAL 54528

// ============================================================
// Kernel 1: transpose x (C,H,W)->(H,W,C')  +  W fragment prep (fp16 hi/lo).
// ============================================================
__global__ void prep_kernel(const float* __restrict__ x,
                            const float* __restrict__ wsrc) {
    __shared__ float ts[64][65];
    const int t = threadIdx.x;

    // W fragment prep: first 18 blocks handle 4608 fragment slots
    if (blockIdx.x < 18) {
        int idx  = blockIdx.x * 256 + t;       // ((k*16)+(kt*4+mt))*32 + lane
        int lane = idx & 31;
        int fm   = (idx >> 5) & 15;
        int k    = idx >> 9;                   // 0..8
        int kt   = fm >> 2;
        int mt   = fm & 3;
        int g    = lane >> 2;
        int tg   = lane & 3;
        int r0   = mt * 16 + g;
        int r1   = r0 + 8;
        int cc0  = kt * 16 + tg * 2;

        uint32_t ah[4], al[4];
        const int rows[4] = {r0, r1, r0, r1};
        const int cols[4] = {cc0, cc0, cc0 + 8, cc0 + 8};
#pragma unroll
        for (int i = 0; i < 4; ++i) {
            float v0 = wsrc[rows[i] * 576 + (cols[i]    ) * 9 + k];
            float v1 = wsrc[rows[i] * 576 + (cols[i] + 1) * 9 + k];
            __half h0 = __float2half_rn(v0);
            __half h1 = __float2half_rn(v1);
            __half l0 = __float2half_rn(v0 - __half2float(h0));
            __half l1 = __float2half_rn(v1 - __half2float(h1));
            uint32_t h0b = (uint32_t)*(uint16_t*)&h0;
            uint32_t h1b = (uint32_t)*(uint16_t*)&h1;
            uint32_t l0b = (uint32_t)*(uint16_t*)&l0;
            uint32_t l1b = (uint32_t)*(uint16_t*)&l1;
            ah[i] = h0b | (h1b << 16);
            al[i] = l0b | (l1b << 16);
        }
        g_wfh[idx] = make_uint4(ah[0], ah[1], ah[2], ah[3]);
        g_wfl[idx] = make_uint4(al[0], al[1], al[2], al[3]);
    }

    // transpose with channel permutation:
    // true channel tx -> slot ((j&7)>>1)*4 + ((j>>3)<<1) + (j&1), j = tx&15
    const int tx = t & 63;
    const int ty = t >> 6;
    const int P0 = blockIdx.x * 64;
    const int j    = tx & 15;
    const int slot = (((j & 7) >> 1) << 2) + ((j >> 3) << 1) + (j & 1);
    const int ptx  = (tx & ~15) | slot;
#pragma unroll
    for (int i = 0; i < 16; ++i) {
        int cch = (i << 2) + ty;
        ts[cch][tx] = x[cch * (IMG_H * IMG_W) + P0 + tx];
    }
    __syncthreads();
#pragma unroll
    for (int i = 0; i < 16; ++i) {
        int p = (i << 2) + ty;
        g_xT[(P0 + p) * 64 + ptx] = ts[tx][p];
    }
}

// ============================================================
// Sample one pixel's 16 fragment channels straight into fp16 B-fragment
// registers. One LDS.128 per (corner, kt); no residual/lo computation.
// ============================================================
__device__ __forceinline__ void sample_px(
    const char* __restrict__ tileb, int c, int ky, int kx,
    float offy, float offx, int gy, int gx, int Y0, int X0,
    uint32_t* BH)
{
    float pyf = (float)(gy - 1 + ky) + offy;
    float pxf = (float)(gx - 1 + kx) + offx;
    float y0f = floorf(pyf), x0f = floorf(pxf);
    int   y0  = (int)y0f,   x0  = (int)x0f;
    float wy1 = pyf - y0f,  wx1 = pxf - x0f;
    float wy0 = 1.f - wy1,  wx0 = 1.f - wx1;
    int iy = y0 - (Y0 - 1);
    int ix = x0 - (X0 - 1);
    float fy0 = ((unsigned)y0       < 256u && (unsigned)iy       <= 17u) ? 1.f : 0.f;
    float fy1 = ((unsigned)(y0 + 1) < 256u && (unsigned)(iy + 1) <= 18u) ? 1.f : 0.f;
    float fx0 = ((unsigned)x0       < 256u && (unsigned)ix       <=  9u) ? 1.f : 0.f;
    float fx1 = ((unsigned)(x0 + 1) < 256u && (unsigned)(ix + 1) <= 10u) ? 1.f : 0.f;
    u64 W00 = splat2(wy0 * wx0 * fy0 * fx0);
    u64 W01 = splat2(wy0 * wx1 * fy0 * fx1);
    u64 W10 = splat2(wy1 * wx0 * fy1 * fx0);
    u64 W11 = splat2(wy1 * wx1 * fy1 * fx1);
    int iyc = min(max(iy, 0), 17);
    int ixc = min(max(ix, 0), 9);
    int c00 = iyc * 11 + ixc;
    int c01 = c00 + 1;
    int c10 = c00 + 11;
    int c11 = c00 + 12;
    const char* p00 = tileb + (c00 << 8) + ((c ^ (c00 & 3)) << 4);
    const char* p01 = tileb + (c01 << 8) + ((c ^ (c01 & 3)) << 4);
    const char* p10 = tileb + (c10 << 8) + ((c ^ (c10 & 3)) << 4);
    const char* p11 = tileb + (c11 << 8) + ((c ^ (c11 & 3)) << 4);
    const uint32_t b00 = (uint32_t)((c00 & 4) << 4);
    const uint32_t b01 = (uint32_t)((c01 & 4) << 4);
    const uint32_t b10 = (uint32_t)((c10 & 4) << 4);
    const uint32_t b11 = (uint32_t)((c11 & 4) << 4);
#pragma unroll
    for (int kt = 0; kt < 4; ++kt) {
        const uint32_t ko = (uint32_t)(kt << 6);
        ulonglong2 v00 = *(const ulonglong2*)(p00 + (ko ^ b00));
        ulonglong2 v01 = *(const ulonglong2*)(p01 + (ko ^ b01));
        ulonglong2 v10 = *(const ulonglong2*)(p10 + (ko ^ b10));
        ulonglong2 v11 = *(const ulonglong2*)(p11 + (ko ^ b11));
        u64 lo = fma2(v00.x, W00, fma2(v01.x, W01, fma2(v10.x, W10, mul2(v11.x, W11))));
        u64 hi = fma2(v00.y, W00, fma2(v01.y, W01, fma2(v10.y, W10, mul2(v11.y, W11))));
        float2 f0 = unpack2(lo);   // true ch 2c, 2c+1   -> b0
        float2 f1 = unpack2(hi);   // true ch 2c+8, 2c+9 -> b1
        uint32_t h0, h1;
        asm("cvt.rn.f16x2.f32 %0, %1, %2;" : "=r"(h0) : "f"(f0.y), "f"(f0.x));
        asm("cvt.rn.f16x2.f32 %0, %1, %2;" : "=r"(h1) : "f"(f1.y), "f"(f1.x));
        BH[kt * 2]     = h0;
        BH[kt * 2 + 1] = h1;
    }
}

// ============================================================
// Kernel 2: main — 16x8 px tile, 256 threads (8 warps), 2 blocks/SM.
//   Warp = 64 cout x 16 px. Samples -> fp16 B-fragment registers; W (fp16
//   hi/lo) fragments LDG'd per warp from fragment-linear global.
//   ZERO block-wide syncs in the tap loop. D = (Wh + Wl) · S.
// ============================================================
extern __shared__ char smc[];

__global__ __launch_bounds__(256, 2)
void deform_main_kernel(const float* __restrict__ offs,
                        const float* __restrict__ bias,
                        float* __restrict__ out) {
    const char* tileb = smc + OFF_TILE;
    float* tilef = (float*)(smc + OFF_TILE);

    const int t    = threadIdx.x;
    const int lane = t & 31;
    const int wid  = t >> 5;
    const int X0   = blockIdx.x << 3;      // 8 wide
    const int Y0   = blockIdx.y << 4;      // 16 tall

    if (t < 64) ((float*)(smc + OFF_BIAS))[t] = bias[t];

    // fragment/sampling identity: quad of lanes per pixel
    const int c    = lane & 3;             // channel group
    const int gx   = X0 + (lane >> 2);     // 0..7
    const int gy0  = Y0 + (wid << 1);      // rows wid*2 (nt=0), +1 (nt=1)
    const int pix0 = (gy0 << 8) + gx;
    const int pix1 = pix0 + 256;

    // tap-0 offsets
    float oy[2], ox[2];
    oy[0] = offs[pix0];  ox[0] = offs[(1 << 16) + pix0];
    oy[1] = offs[pix1];  ox[1] = offs[(1 << 16) + pix1];

    // ---- halo tile: 19x11 cells x 64 ch fp32 (zero outside image) ----
    for (int f = t; f < 209 * 16; f += 256) {
        int cell = f >> 4;
        int q    = f & 15;
        int rr   = cell / 11;
        int cc   = cell - rr * 11;
        int hy   = Y0 - 1 + rr;
        int hx   = X0 - 1 + cc;
        float4 v = make_float4(0.f, 0.f, 0.f, 0.f);
        if ((unsigned)hy < (unsigned)IMG_H && (unsigned)hx < (unsigned)IMG_W)
            v = *reinterpret_cast<const float4*>(
                    &g_xT[(((hy << 8) + hx) << 6) + (q << 2)]);
        *reinterpret_cast<float4*>(
            &tilef[(cell << 6) + ((q ^ (cell & 7)) << 2)]) = v;
    }
    __syncthreads();     // halo + bias visible — the ONLY block-wide sync

    float acc[4][2][4];
#pragma unroll
    for (int m = 0; m < 4; ++m)
#pragma unroll
        for (int n = 0; n < 2; ++n)
#pragma unroll
            for (int j = 0; j < 4; ++j) acc[m][n][j] = 0.f;

    uint32_t BH[2][8];

#pragma unroll 1
    for (int k = 0; k < 9; ++k) {
        const int ky = k / 3;
        const int kx = k - ky * 3;

        // prefetch offsets for tap k+1
        float noy[2], nox[2];
        if (k < 8) {
            noy[0] = offs[(((k + 1) * 2    ) << 16) + pix0];
            nox[0] = offs[(((k + 1) * 2 + 1) << 16) + pix0];
            noy[1] = offs[(((k + 1) * 2    ) << 16) + pix1];
            nox[1] = offs[(((k + 1) * 2 + 1) << 16) + pix1];
        }

        // ---- sample tap k into fp16 B-fragment registers (no sync) ----
        sample_px(tileb, c, ky, kx, oy[0], ox[0], gy0,     gx, Y0, X0, BH[0]);
        sample_px(tileb, c, ky, kx, oy[1], ox[1], gy0 + 1, gx, Y0, X0, BH[1]);

        // ---- MMA(k): 64 HMMA per warp (hh + lh), W frags via LDG ----
        {
            const uint4* __restrict__ wfh = g_wfh + k * 512 + lane;
            const uint4* __restrict__ wfl = g_wfl + k * 512 + lane;
#pragma unroll
            for (int kt = 0; kt < 4; ++kt) {
#pragma unroll
                for (int mt = 0; mt < 4; ++mt) {
                    uint4 AH = __ldg(wfh + ((kt << 2) | mt) * 32);
                    uint4 AL = __ldg(wfl + ((kt << 2) | mt) * 32);
                    mma2(acc[mt][0], &AH.x, BH[0][kt * 2], BH[0][kt * 2 + 1]);
                    mma2(acc[mt][1], &AH.x, BH[1][kt * 2], BH[1][kt * 2 + 1]);
                    mma2(acc[mt][0], &AL.x, BH[0][kt * 2], BH[0][kt * 2 + 1]);
                    mma2(acc[mt][1], &AL.x, BH[1][kt * 2], BH[1][kt * 2 + 1]);
                }
            }
        }

        oy[0] = noy[0]; ox[0] = nox[0];
        oy[1] = noy[1]; ox[1] = nox[1];
    }

    // ---- epilogue: bias + float2 stores (acc is warp-local; no sync) ----
    {
        const float* sbias = (const float*)(smc + OFF_BIAS);
        int tg  = lane >> 2;
        int tc2 = (lane & 3) << 1;
#pragma unroll
        for (int mt = 0; mt < 4; ++mt) {
            int c0 = mt * 16 + tg;
            int c1 = c0 + 8;
            float b0 = sbias[c0], b1 = sbias[c1];
#pragma unroll
            for (int nt = 0; nt < 2; ++nt) {
                int pix = ((gy0 + nt) << 8) + X0 + tc2;
                *reinterpret_cast<float2*>(&out[(c0 << 16) + pix]) =
                    make_float2(acc[mt][nt][0] + b0, acc[mt][nt][1] + b0);
                *reinterpret_cast<float2*>(&out[(c1 << 16) + pix]) =
                    make_float2(acc[mt][nt][2] + b1, acc[mt][nt][3] + b1);
            }
        }
    }
}

// ============================================================
// Launch
// ============================================================
extern "C" void kernel_launch(void* const* d_in, const int* in_sizes, int n_in,
                              void* d_out, int out_size) {
    const float* x      = nullptr;
    const float* offset = nullptr;
    const float* weight = nullptr;
    const float* bias   = nullptr;

    for (int i = 0; i < n_in; ++i) {
        switch (in_sizes[i]) {
            case 64 * 256 * 256: x      = (const float*)d_in[i]; break;
            case 18 * 256 * 256: offset = (const float*)d_in[i]; break;
            case 64 * 64 * 9:    weight = (const float*)d_in[i]; break;
            case 64:             bias   = (const float*)d_in[i]; break;
            default: break;
        }
    }
    if (!x || !offset || !weight || !bias) {
        x      = (const float*)d_in[0];
        offset = (const float*)d_in[1];
        weight = (const float*)d_in[2];
        bias   = (const float*)d_in[3];
    }

    cudaFuncSetAttribute(deform_main_kernel,
                         cudaFuncAttributeMaxDynamicSharedMemorySize, SMEM_TOTAL);

    prep_kernel<<<(IMG_H * IMG_W) / 64, 256>>>(x, weight);
    deform_main_kernel<<<dim3(IMG_W / 8, IMG_H / 16), 256, SMEM_TOTAL>>>(
        offset, bias, (float*)d_out);
}

// round 14
// speedup vs baseline: 1.6006x; 1.3589x over previous
#include <cuda_runtime.h>
#include <cuda_fp16.h>
#include <cstdint>

// Problem constants: B=1, CIN=COUT=64, H=W=256, K=3, stride=1, pad=1.
#define IMG_H 256
#define IMG_W 256

// ---- device scratch (no allocation allowed) ----
// g_xh: x as (y, x, c') fp16, channels permuted into fragment-pair chunks:
// 16B chunk (2c + p), c=0..3, p=0..1 holds true channels
//   {2c,2c+1,2c+8,2c+9}+32p  (halfs 0-3)  and  +32p+16 (halfs 4-7)
// so one 16B read gives lane-group c its B-fragment b0/b1 for kt=2p,2p+1.
__device__ __half g_xh[IMG_H * IMG_W * 64];
// W in MMA A-fragment-linear layout (fp16 hi/lo split), as in R12.
__device__ uint4 g_wfh[9 * 16 * 32];
__device__ uint4 g_wfl[9 * 16 * 32];

typedef unsigned long long u64;

__device__ __forceinline__ __half2 u2h(uint32_t v) {
    return *reinterpret_cast<__half2*>(&v);
}
__device__ __forceinline__ uint32_t h2u(__half2 v) {
    return *reinterpret_cast<uint32_t*>(&v);
}

// ---- tensor-core helpers (sm_80 path; compiles for compute_100) ----
__device__ __forceinline__ void mma2(float* c, const uint32_t* a,
                                     uint32_t b0, uint32_t b1) {
    asm volatile(
        "mma.sync.aligned.m16n8k16.row.col.f32.f16.f16.f32 "
        "{%0,%1,%2,%3}, {%4,%5,%6,%7}, {%8,%9}, {%0,%1,%2,%3};"
        : "+f"(c[0]), "+f"(c[1]), "+f"(c[2]), "+f"(c[3])
        : "r"(a[0]), "r"(a[1]), "r"(a[2]), "r"(a[3]), "r"(b0), "r"(b1));
}

// ---- smem layout (bytes from dynamic base) ----
#define OFF_BIAS   0          // 64 floats
#define OFF_TILE   1024       // halo fp16: 19*11 cells * 128 B = 26752
#define SMEM_TOTAL 27776

// ============================================================
// Kernel 1: transpose x (C,H,W)->(H,W,C') fp16  +  W fragment prep.
// ============================================================
__global__ void prep_kernel(const float* __restrict__ x,
                            const float* __restrict__ wsrc) {
    __shared__ float ts[64][65];
    const int t = threadIdx.x;

    // W fragment prep: first 18 blocks handle 4608 fragment slots
    if (blockIdx.x < 18) {
        int idx  = blockIdx.x * 256 + t;       // ((k*16)+(kt*4+mt))*32 + lane
        int lane = idx & 31;
        int fm   = (idx >> 5) & 15;
        int k    = idx >> 9;                   // 0..8
        int kt   = fm >> 2;
        int mt   = fm & 3;
        int g    = lane >> 2;
        int tg   = lane & 3;
        int r0   = mt * 16 + g;
        int r1   = r0 + 8;
        int cc0  = kt * 16 + tg * 2;

        uint32_t ah[4], al[4];
        const int rows[4] = {r0, r1, r0, r1};
        const int cols[4] = {cc0, cc0, cc0 + 8, cc0 + 8};
#pragma unroll
        for (int i = 0; i < 4; ++i) {
            float v0 = wsrc[rows[i] * 576 + (cols[i]    ) * 9 + k];
            float v1 = wsrc[rows[i] * 576 + (cols[i] + 1) * 9 + k];
            __half h0 = __float2half_rn(v0);
            __half h1 = __float2half_rn(v1);
            __half l0 = __float2half_rn(v0 - __half2float(h0));
            __half l1 = __float2half_rn(v1 - __half2float(h1));
            uint32_t h0b = (uint32_t)*(uint16_t*)&h0;
            uint32_t h1b = (uint32_t)*(uint16_t*)&h1;
            uint32_t l0b = (uint32_t)*(uint16_t*)&l0;
            uint32_t l1b = (uint32_t)*(uint16_t*)&l1;
            ah[i] = h0b | (h1b << 16);
            al[i] = l0b | (l1b << 16);
        }
        g_wfh[idx] = make_uint4(ah[0], ah[1], ah[2], ah[3]);
        g_wfl[idx] = make_uint4(al[0], al[1], al[2], al[3]);
    }

    // transpose + fragment-pair channel permutation + fp16 convert.
    // true channel tx -> half-slot: chunk = 2*((tx&7)>>1) + ((tx>>4)&1... )
    const int tx = t & 63;
    const int ty = t >> 6;
    const int P0 = blockIdx.x * 64;
    const int kt   = tx >> 4;            // 0..3
    const int r    = tx & 15;
    const int cgrp = (r & 7) >> 1;       // 0..3
    const int h    = r >> 3;             // 0/1 (b0/b1)
    const int chunk = (cgrp << 1) + (kt >> 1);
    const int pos   = ((kt & 1) << 2) + (h << 1) + (r & 1);
    const int ptx   = (chunk << 3) + pos;
#pragma unroll
    for (int i = 0; i < 16; ++i) {
        int cch = (i << 2) + ty;
        ts[cch][tx] = x[cch * (IMG_H * IMG_W) + P0 + tx];
    }
    __syncthreads();
#pragma unroll
    for (int i = 0; i < 16; ++i) {
        int p = (i << 2) + ty;
        g_xh[(P0 + p) * 64 + ptx] = __float2half_rn(ts[tx][p]);
    }
}

// ============================================================
// Sample one pixel's 16 fragment channels: 8 LDS.128 + HFMA2 bilinear,
// results drop directly into fp16 B-fragment regs (BH[kt*2+h]).
// ============================================================
__device__ __forceinline__ void sample_px(
    const char* __restrict__ tileb, int cc2, int ky, int kx,
    float offy, float offx, int gy, int gx, int Y0, int X0,
    uint32_t* BH)
{
    float pyf = (float)(gy - 1 + ky) + offy;
    float pxf = (float)(gx - 1 + kx) + offx;
    float y0f = floorf(pyf), x0f = floorf(pxf);
    int   y0  = (int)y0f,   x0  = (int)x0f;
    float wy1 = pyf - y0f,  wx1 = pxf - x0f;
    float wy0 = 1.f - wy1,  wx0 = 1.f - wx1;
    int iy = y0 - (Y0 - 1);
    int ix = x0 - (X0 - 1);
    float fy0 = ((unsigned)y0       < 256u && (unsigned)iy       <= 17u) ? 1.f : 0.f;
    float fy1 = ((unsigned)(y0 + 1) < 256u && (unsigned)(iy + 1) <= 18u) ? 1.f : 0.f;
    float fx0 = ((unsigned)x0       < 256u && (unsigned)ix       <=  9u) ? 1.f : 0.f;
    float fx1 = ((unsigned)(x0 + 1) < 256u && (unsigned)(ix + 1) <= 10u) ? 1.f : 0.f;
    __half2 W00 = __float2half2_rn(wy0 * wx0 * fy0 * fx0);
    __half2 W01 = __float2half2_rn(wy0 * wx1 * fy0 * fx1);
    __half2 W10 = __float2half2_rn(wy1 * wx0 * fy1 * fx0);
    __half2 W11 = __float2half2_rn(wy1 * wx1 * fy1 * fx1);
    int iyc = min(max(iy, 0), 17);
    int ixc = min(max(ix, 0), 9);
    int c00 = iyc * 11 + ixc;
    int c01 = c00 + 1;
    int c10 = c00 + 11;
    int c11 = c00 + 12;
    // cell stride 128 B; chunk swizzle: (chunk ^ (cell&7)) << 4; p=1 -> addr ^ 0x10
    uint32_t a00 = (uint32_t)((c00 << 7) + ((cc2 ^ (c00 & 7)) << 4));
    uint32_t a01 = (uint32_t)((c01 << 7) + ((cc2 ^ (c01 & 7)) << 4));
    uint32_t a10 = (uint32_t)((c10 << 7) + ((cc2 ^ (c10 & 7)) << 4));
    uint32_t a11 = (uint32_t)((c11 << 7) + ((cc2 ^ (c11 & 7)) << 4));
#pragma unroll
    for (int p = 0; p < 2; ++p) {
        const uint32_t pp = (uint32_t)(p << 4);
        uint4 v00 = *(const uint4*)(tileb + (a00 ^ pp));
        uint4 v01 = *(const uint4*)(tileb + (a01 ^ pp));
        uint4 v10 = *(const uint4*)(tileb + (a10 ^ pp));
        uint4 v11 = *(const uint4*)(tileb + (a11 ^ pp));
        __half2 b0 = __hfma2(W11, u2h(v11.x), __hfma2(W10, u2h(v10.x),
                     __hfma2(W01, u2h(v01.x), __hmul2(W00, u2h(v00.x)))));
        __half2 b1 = __hfma2(W11, u2h(v11.y), __hfma2(W10, u2h(v10.y),
                     __hfma2(W01, u2h(v01.y), __hmul2(W00, u2h(v00.y)))));
        __half2 b2 = __hfma2(W11, u2h(v11.z), __hfma2(W10, u2h(v10.z),
                     __hfma2(W01, u2h(v01.z), __hmul2(W00, u2h(v00.z)))));
        __half2 b3 = __hfma2(W11, u2h(v11.w), __hfma2(W10, u2h(v10.w),
                     __hfma2(W01, u2h(v01.w), __hmul2(W00, u2h(v00.w)))));
        BH[4 * p + 0] = h2u(b0);   // b0 of kt=2p
        BH[4 * p + 1] = h2u(b1);   // b1 of kt=2p
        BH[4 * p + 2] = h2u(b2);   // b0 of kt=2p+1
        BH[4 * p + 3] = h2u(b3);   // b1 of kt=2p+1
    }
}

// ============================================================
// Kernel 2: main — 16x8 px tile, 256 threads (8 warps), 2 blocks/SM.
//   fp16 halo tile; samples -> fp16 B-fragments via HFMA2; W (fp16 hi/lo)
//   fragments LDG'd from fragment-linear global. Zero syncs in tap loop.
// ============================================================
extern __shared__ char smc[];

__global__ __launch_bounds__(256, 2)
void deform_main_kernel(const float* __restrict__ offs,
                        const float* __restrict__ bias,
                        float* __restrict__ out) {
    const char* tileb = smc + OFF_TILE;

    const int t    = threadIdx.x;
    const int lane = t & 31;
    const int wid  = t >> 5;
    const int X0   = blockIdx.x << 3;      // 8 wide
    const int Y0   = blockIdx.y << 4;      // 16 tall

    if (t < 64) ((float*)(smc + OFF_BIAS))[t] = bias[t];

    // fragment/sampling identity: quad of lanes per pixel
    const int cc2  = (lane & 3) << 1;      // chunk base = 2c
    const int gx   = X0 + (lane >> 2);     // 0..7
    const int gy0  = Y0 + (wid << 1);      // rows wid*2 (nt=0), +1 (nt=1)
    const int pix0 = (gy0 << 8) + gx;
    const int pix1 = pix0 + 256;

    // tap-0 offsets
    float oy[2], ox[2];
    oy[0] = offs[pix0];  ox[0] = offs[(1 << 16) + pix0];
    oy[1] = offs[pix1];  ox[1] = offs[(1 << 16) + pix1];

    // ---- halo tile: 19x11 cells x 128 B fp16 (zero outside image) ----
    for (int f = t; f < 209 * 8; f += 256) {
        int cell = f >> 3;
        int q    = f & 7;
        int rr   = cell / 11;
        int cc   = cell - rr * 11;
        int hy   = Y0 - 1 + rr;
        int hx   = X0 - 1 + cc;
        uint4 v = make_uint4(0u, 0u, 0u, 0u);
        if ((unsigned)hy < (unsigned)IMG_H && (unsigned)hx < (unsigned)IMG_W)
            v = *reinterpret_cast<const uint4*>(
                    &g_xh[(((hy << 8) + hx) << 6) + (q << 3)]);
        *reinterpret_cast<uint4*>(
            const_cast<char*>(tileb) + (cell << 7) + ((q ^ (cell & 7)) << 4)) = v;
    }
    __syncthreads();     // halo + bias visible — the ONLY block-wide sync

    float acc[4][2][4];
#pragma unroll
    for (int m = 0; m < 4; ++m)
#pragma unroll
        for (int n = 0; n < 2; ++n)
#pragma unroll
            for (int j = 0; j < 4; ++j) acc[m][n][j] = 0.f;

    uint32_t BH[2][8];

#pragma unroll 1
    for (int k = 0; k < 9; ++k) {
        const int ky = k / 3;
        const int kx = k - ky * 3;

        // prefetch offsets for tap k+1
        float noy[2], nox[2];
        if (k < 8) {
            noy[0] = offs[(((k + 1) * 2    ) << 16) + pix0];
            nox[0] = offs[(((k + 1) * 2 + 1) << 16) + pix0];
            noy[1] = offs[(((k + 1) * 2    ) << 16) + pix1];
            nox[1] = offs[(((k + 1) * 2 + 1) << 16) + pix1];
        }

        // ---- sample tap k into fp16 B-fragment registers (no sync) ----
        sample_px(tileb, cc2, ky, kx, oy[0], ox[0], gy0,     gx, Y0, X0, BH[0]);
        sample_px(tileb, cc2, ky, kx, oy[1], ox[1], gy0 + 1, gx, Y0, X0, BH[1]);

        // ---- MMA(k): 64 HMMA per warp (hh + lh), W frags via LDG ----
        {
            const uint4* __restrict__ wfh = g_wfh + k * 512 + lane;
            const uint4* __restrict__ wfl = g_wfl + k * 512 + lane;
#pragma unroll
            for (int kt = 0; kt < 4; ++kt) {
#pragma unroll
                for (int mt = 0; mt < 4; ++mt) {
                    uint4 AH = __ldg(wfh + ((kt << 2) | mt) * 32);
                    uint4 AL = __ldg(wfl + ((kt << 2) | mt) * 32);
                    mma2(acc[mt][0], &AH.x, BH[0][kt * 2], BH[0][kt * 2 + 1]);
                    mma2(acc[mt][1], &AH.x, BH[1][kt * 2], BH[1][kt * 2 + 1]);
                    mma2(acc[mt][0], &AL.x, BH[0][kt * 2], BH[0][kt * 2 + 1]);
                    mma2(acc[mt][1], &AL.x, BH[1][kt * 2], BH[1][kt * 2 + 1]);
                }
            }
        }

        oy[0] = noy[0]; ox[0] = nox[0];
        oy[1] = noy[1]; ox[1] = nox[1];
    }

    // ---- epilogue: bias + float2 stores (acc is warp-local; no sync) ----
    {
        const float* sbias = (const float*)(smc + OFF_BIAS);
        int tg  = lane >> 2;
        int tc2 = (lane & 3) << 1;
#pragma unroll
        for (int mt = 0; mt < 4; ++mt) {
            int c0 = mt * 16 + tg;
            int c1 = c0 + 8;
            float b0 = sbias[c0], b1 = sbias[c1];
#pragma unroll
            for (int nt = 0; nt < 2; ++nt) {
                int pix = ((gy0 + nt) << 8) + X0 + tc2;
                *reinterpret_cast<float2*>(&out[(c0 << 16) + pix]) =
                    make_float2(acc[mt][nt][0] + b0, acc[mt][nt][1] + b0);
                *reinterpret_cast<float2*>(&out[(c1 << 16) + pix]) =
                    make_float2(acc[mt][nt][2] + b1, acc[mt][nt][3] + b1);
            }
        }
    }
}

// ============================================================
// Launch
// ============================================================
extern "C" void kernel_launch(void* const* d_in, const int* in_sizes, int n_in,
                              void* d_out, int out_size) {
    const float* x      = nullptr;
    const float* offset = nullptr;
    const float* weight = nullptr;
    const float* bias   = nullptr;

    for (int i = 0; i < n_in; ++i) {
        switch (in_sizes[i]) {
            case 64 * 256 * 256: x      = (const float*)d_in[i]; break;
            case 18 * 256 * 256: offset = (const float*)d_in[i]; break;
            case 64 * 64 * 9:    weight = (const float*)d_in[i]; break;
            case 64:             bias   = (const float*)d_in[i]; break;
            default: break;
        }
    }
    if (!x || !offset || !weight || !bias) {
        x      = (const float*)d_in[0];
        offset = (const float*)d_in[1];
        weight = (const float*)d_in[2];
        bias   = (const float*)d_in[3];
    }

    cudaFuncSetAttribute(deform_main_kernel,
                         cudaFuncAttributeMaxDynamicSharedMemorySize, SMEM_TOTAL);

    prep_kernel<<<(IMG_H * IMG_W) / 64, 256>>>(x, weight);
    deform_main_kernel<<<dim3(IMG_W / 8, IMG_H / 16), 256, SMEM_TOTAL>>>(
        offset, bias, (float*)d_out);
}